// round 5
// baseline (speedup 1.0000x reference)
#include <cuda_runtime.h>
#include <math.h>
#include <stdint.h>

#define Bsz 4
#define Nn 1024
#define IND 128
#define Dd 512
#define Hh 8
#define HDd 64
#define Ee 4
#define Ll 3
#define BNROWS (Bsz*Nn)   // 4096

// Scratch (device globals: no cudaMalloc allowed)
__device__ float g_h [BNROWS*Dd];
__device__ float g_q [BNROWS*Dd];
__device__ float g_k [BNROWS*Dd];
__device__ float g_v [BNROWS*Dd];
__device__ float g_ao[BNROWS*Dd];

// ---------------------------------------------------------------------------
// tf32 helpers
// ---------------------------------------------------------------------------
__device__ __forceinline__ float f2tf(float x) {
    uint32_t u;
    asm("cvt.rna.tf32.f32 %0, %1;" : "=r"(u) : "f"(x));
    return __uint_as_float(u);
}

__device__ __forceinline__ void mma8(float* c, float a0, float a1, float a2, float a3,
                                     float b0, float b1) {
    uint32_t A0 = __float_as_uint(a0), A1 = __float_as_uint(a1);
    uint32_t A2 = __float_as_uint(a2), A3 = __float_as_uint(a3);
    uint32_t B0 = __float_as_uint(b0), B1 = __float_as_uint(b1);
    asm volatile(
        "mma.sync.aligned.m16n8k8.row.col.f32.tf32.tf32.f32 "
        "{%0,%1,%2,%3},{%4,%5,%6,%7},{%8,%9},{%0,%1,%2,%3};"
        : "+f"(c[0]), "+f"(c[1]), "+f"(c[2]), "+f"(c[3])
        : "r"(A0), "r"(A1), "r"(A2), "r"(A3), "r"(B0), "r"(B1));
}

// ---------------------------------------------------------------------------
// tf32 GEMM body, two-stage smem pipeline.
// CTA tile 128x64, BK=32, 8 warps (4x2), warp tile 32x32.
// As: [2][128][36]; Bs: [2][32][72].
// ---------------------------------------------------------------------------
#define GA_STR 36
#define GB_STR 72
#define GEMM_SMEM ((2*128*GA_STR + 2*32*GB_STR)*4)

template<bool RES>
__device__ __forceinline__
void gemm_body(const float* __restrict__ A, const float* __restrict__ W,
               const float* __restrict__ bias, const float* __restrict__ res,
               float* __restrict__ C, int K, int Nc, float* sm,
               int bm, int bn) {
    float* As = sm;                    // [2][128*GA_STR]
    float* Bs = sm + 2*128*GA_STR;     // [2][32*GB_STR]

    const int tid  = threadIdx.x;
    const int lane = tid & 31;
    const int warp = tid >> 5;
    const int wm   = warp & 3;
    const int wn   = warp >> 2;
    const int g    = lane >> 2;
    const int tg   = lane & 3;

    const int ar = tid >> 3;            // 0..31
    const int ac = (tid & 7) << 2;      // 0..28
    const int br = tid >> 4;            // 0..15
    const int bc = (tid & 15) << 2;     // 0..60

    float4 ra[4], rb[2];

    auto LD = [&](int k0) {
        #pragma unroll
        for (int p = 0; p < 4; p++)
            ra[p] = *(const float4*)(A + (size_t)(bm + ar + 32*p)*K + k0 + ac);
        #pragma unroll
        for (int p = 0; p < 2; p++)
            rb[p] = *(const float4*)(W + (size_t)(k0 + br + 16*p)*Nc + bn + bc);
    };
    auto ST = [&](int st) {
        float* as = As + st*128*GA_STR;
        float* bs = Bs + st*32*GB_STR;
        #pragma unroll
        for (int p = 0; p < 4; p++) {
            float4 t;
            t.x = f2tf(ra[p].x); t.y = f2tf(ra[p].y);
            t.z = f2tf(ra[p].z); t.w = f2tf(ra[p].w);
            *(float4*)(as + (ar + 32*p)*GA_STR + ac) = t;
        }
        #pragma unroll
        for (int p = 0; p < 2; p++) {
            float4 t;
            t.x = f2tf(rb[p].x); t.y = f2tf(rb[p].y);
            t.z = f2tf(rb[p].z); t.w = f2tf(rb[p].w);
            *(float4*)(bs + (br + 16*p)*GB_STR + bc) = t;
        }
    };

    float acc[2][4][4];
    #pragma unroll
    for (int mt = 0; mt < 2; mt++)
        #pragma unroll
        for (int nt = 0; nt < 4; nt++)
            #pragma unroll
            for (int e = 0; e < 4; e++) acc[mt][nt][e] = 0.f;

    LD(0); ST(0); __syncthreads();

    const int T = K >> 5;
    for (int t = 0; t < T; t++) {
        if (t + 1 < T) LD((t + 1) << 5);

        const float* as = As + (t & 1)*128*GA_STR;
        const float* bs = Bs + (t & 1)*32*GB_STR;
        #pragma unroll
        for (int kk = 0; kk < 4; kk++) {
            const int kb = kk * 8;
            float a[2][4];
            #pragma unroll
            for (int mt = 0; mt < 2; mt++) {
                const int r = wm*32 + mt*16;
                a[mt][0] = as[(r + g    )*GA_STR + kb + tg    ];
                a[mt][1] = as[(r + g + 8)*GA_STR + kb + tg    ];
                a[mt][2] = as[(r + g    )*GA_STR + kb + tg + 4];
                a[mt][3] = as[(r + g + 8)*GA_STR + kb + tg + 4];
            }
            float b[4][2];
            #pragma unroll
            for (int nt = 0; nt < 4; nt++) {
                const int cc = wn*32 + nt*8 + g;
                b[nt][0] = bs[(kb + tg    )*GB_STR + cc];
                b[nt][1] = bs[(kb + tg + 4)*GB_STR + cc];
            }
            #pragma unroll
            for (int mt = 0; mt < 2; mt++)
                #pragma unroll
                for (int nt = 0; nt < 4; nt++)
                    mma8(acc[mt][nt], a[mt][0], a[mt][1], a[mt][2], a[mt][3],
                         b[nt][0], b[nt][1]);
        }

        if (t + 1 < T) {
            ST((t + 1) & 1);
            __syncthreads();
        }
    }

    #pragma unroll
    for (int mt = 0; mt < 2; mt++) {
        const int r0 = bm + wm*32 + mt*16 + g;
        #pragma unroll
        for (int nt = 0; nt < 4; nt++) {
            const int cc = bn + wn*32 + nt*8 + 2*tg;
            const float b0 = bias[cc], b1 = bias[cc + 1];
            float2 o0, o1;
            o0.x = acc[mt][nt][0] + b0; o0.y = acc[mt][nt][1] + b1;
            o1.x = acc[mt][nt][2] + b0; o1.y = acc[mt][nt][3] + b1;
            const size_t off0 = (size_t)r0*Nc + cc;
            const size_t off1 = (size_t)(r0 + 8)*Nc + cc;
            if (RES) {
                float2 p0 = *(const float2*)(res + off0);
                float2 p1 = *(const float2*)(res + off1);
                o0.x += p0.x; o0.y += p0.y; o1.x += p1.x; o1.y += p1.y;
            }
            *(float2*)(C + off0) = o0;
            *(float2*)(C + off1) = o1;
        }
    }
}

template<bool RES>
__global__ __launch_bounds__(256)
void gemm_tf32(const float* __restrict__ A, const float* __restrict__ W,
               const float* __restrict__ bias, const float* __restrict__ res,
               float* __restrict__ C, int K, int Nc) {
    extern __shared__ float sm[];
    gemm_body<RES>(A, W, bias, res, C, K, Nc, sm,
                   blockIdx.x * 128, blockIdx.y * 64);
}

// Fused Q/K/V projection: blockIdx.z selects which of the three GEMMs.
__global__ __launch_bounds__(256)
void qkv_tf32(const float* __restrict__ h,
              const float* __restrict__ qw, const float* __restrict__ qb,
              const float* __restrict__ kw, const float* __restrict__ kb,
              const float* __restrict__ vw, const float* __restrict__ vb,
              float* __restrict__ q, float* __restrict__ k, float* __restrict__ v) {
    extern __shared__ float sm[];
    const int z = blockIdx.z;
    const float* W  = (z == 0) ? qw : (z == 1) ? kw : vw;
    const float* Bi = (z == 0) ? qb : (z == 1) ? kb : vb;
    float*       C  = (z == 0) ? q  : (z == 1) ? k  : v;
    gemm_body<false>(h, W, Bi, nullptr, C, Dd, Dd, sm,
                     blockIdx.x * 128, blockIdx.y * 64);
}

// ---------------------------------------------------------------------------
// tf32 flash attention with edge bias (decoupled edge accumulation).
// CTA = (head, 128-row i-tile, batch). 8 warps, warp w owns rows w*16..+15.
// ---------------------------------------------------------------------------
#define QSTR 68
#define KSTR 72
#define ATTN_SMEM ((128*QSTR + 64*KSTR + 64*KSTR + 128*QSTR)*4)

__global__ __launch_bounds__(256, 2)
void attn_tf32(const float* __restrict__ q, const float* __restrict__ k,
               const float* __restrict__ v, const float* __restrict__ edges,
               const float* __restrict__ ew, const float* __restrict__ eb,
               float* __restrict__ ao) {
    extern __shared__ float sm[];
    float* Qs = sm;                       // [128][QSTR]
    float* Ks = Qs + 128*QSTR;            // [64][KSTR] (d-major)
    float* Vs = Ks + 64*KSTR;             // [64][KSTR] (j-major)
    float* Ps = Vs + 64*KSTR;             // [128][QSTR]

    const int tid  = threadIdx.x;
    const int lane = tid & 31;
    const int w    = tid >> 5;
    const int g    = lane >> 2;
    const int tg   = lane & 3;
    const int hh   = blockIdx.x;
    const int i0   = blockIdx.y * 128;
    const int bb   = blockIdx.z;
    const int w16  = w * 16;

    const float ew0 = ew[hh], ew1 = ew[Hh + hh];
    const float ew2 = ew[2*Hh + hh], ew3 = ew[3*Hh + hh];
    const float ebh = eb[hh];

    const int lr = tid >> 2;             // 0..63
    const int lc = (tid & 3) << 2;       // 0,4,8,12

    // Load Q (scaled by 0.125, tf32): rows lr, lr+64
    #pragma unroll
    for (int rr = 0; rr < 2; rr++) {
        const int r = lr + rr*64;
        const float* qp = q + ((size_t)(bb*Nn + i0 + r))*Dd + hh*HDd;
        #pragma unroll
        for (int p = 0; p < 4; p++) {
            const int d = lc + p*16;
            float4 a = *(const float4*)(qp + d);
            float4 t;
            t.x = f2tf(a.x * 0.125f); t.y = f2tf(a.y * 0.125f);
            t.z = f2tf(a.z * 0.125f); t.w = f2tf(a.w * 0.125f);
            *(float4*)(Qs + r*QSTR + d) = t;
        }
    }

    float o[8][4];
    #pragma unroll
    for (int dt = 0; dt < 8; dt++)
        #pragma unroll
        for (int e = 0; e < 4; e++) o[dt][e] = 0.f;
    float m0 = -1e30f, m1 = -1e30f, l0 = 0.f, l1 = 0.f;

    const int    r0g = i0 + w16 + g;
    const size_t eb0 = ((size_t)bb*Nn + r0g)*Nn;
    const size_t eb1 = eb0 + 8*(size_t)Nn;

    for (int j0 = 0; j0 < Nn; j0 += 64) {
        __syncthreads();   // previous tile's Ks/Vs reads done

        // stage K (transposed, tf32) + V (tf32)
        {
            const float* kp = k + ((size_t)(bb*Nn + j0 + lr))*Dd + hh*HDd;
            const float* vp = v + ((size_t)(bb*Nn + j0 + lr))*Dd + hh*HDd;
            #pragma unroll
            for (int p = 0; p < 4; p++) {
                const int d = lc + p*16;
                float4 kv = *(const float4*)(kp + d);
                Ks[(d+0)*KSTR + lr] = f2tf(kv.x);
                Ks[(d+1)*KSTR + lr] = f2tf(kv.y);
                Ks[(d+2)*KSTR + lr] = f2tf(kv.z);
                Ks[(d+3)*KSTR + lr] = f2tf(kv.w);
                float4 vv = *(const float4*)(vp + d);
                float4 tv;
                tv.x = f2tf(vv.x); tv.y = f2tf(vv.y);
                tv.z = f2tf(vv.z); tv.w = f2tf(vv.w);
                *(float4*)(Vs + lr*KSTR + d) = tv;
            }
        }

        float s[8][4];
        #pragma unroll
        for (int nt = 0; nt < 8; nt++)
            #pragma unroll
            for (int e = 0; e < 4; e++) s[nt][e] = 0.f;

        // edge bias, first half (nt 0..3) — independent of MMA chain
        float ea[4][4];
        #pragma unroll
        for (int nt = 0; nt < 4; nt++) {
            const int jc = j0 + nt*8 + 2*tg;
            float4 e0 = *(const float4*)(edges + (eb0 + jc    )*Ee);
            float4 e1 = *(const float4*)(edges + (eb0 + jc + 1)*Ee);
            float4 e2 = *(const float4*)(edges + (eb1 + jc    )*Ee);
            float4 e3 = *(const float4*)(edges + (eb1 + jc + 1)*Ee);
            ea[nt][0] = fmaf(e0.x,ew0, fmaf(e0.y,ew1, fmaf(e0.z,ew2, fmaf(e0.w,ew3, ebh))));
            ea[nt][1] = fmaf(e1.x,ew0, fmaf(e1.y,ew1, fmaf(e1.z,ew2, fmaf(e1.w,ew3, ebh))));
            ea[nt][2] = fmaf(e2.x,ew0, fmaf(e2.y,ew1, fmaf(e2.z,ew2, fmaf(e2.w,ew3, ebh))));
            ea[nt][3] = fmaf(e3.x,ew0, fmaf(e3.y,ew1, fmaf(e3.z,ew2, fmaf(e3.w,ew3, ebh))));
        }
        __syncthreads();   // Ks/Vs ready

        // QK MMA, columns 0..31
        #pragma unroll
        for (int kb = 0; kb < 64; kb += 8) {
            const float a0 = Qs[(w16 + g    )*QSTR + kb + tg    ];
            const float a1 = Qs[(w16 + g + 8)*QSTR + kb + tg    ];
            const float a2 = Qs[(w16 + g    )*QSTR + kb + tg + 4];
            const float a3 = Qs[(w16 + g + 8)*QSTR + kb + tg + 4];
            #pragma unroll
            for (int nt = 0; nt < 4; nt++) {
                const float b0 = Ks[(kb + tg    )*KSTR + nt*8 + g];
                const float b1 = Ks[(kb + tg + 4)*KSTR + nt*8 + g];
                mma8(s[nt], a0, a1, a2, a3, b0, b1);
            }
        }
        #pragma unroll
        for (int nt = 0; nt < 4; nt++)
            #pragma unroll
            for (int e = 0; e < 4; e++) s[nt][e] += ea[nt][e];

        // edge bias, second half (nt 4..7) — overlaps with next MMA block
        #pragma unroll
        for (int nt = 0; nt < 4; nt++) {
            const int jc = j0 + (nt + 4)*8 + 2*tg;
            float4 e0 = *(const float4*)(edges + (eb0 + jc    )*Ee);
            float4 e1 = *(const float4*)(edges + (eb0 + jc + 1)*Ee);
            float4 e2 = *(const float4*)(edges + (eb1 + jc    )*Ee);
            float4 e3 = *(const float4*)(edges + (eb1 + jc + 1)*Ee);
            ea[nt][0] = fmaf(e0.x,ew0, fmaf(e0.y,ew1, fmaf(e0.z,ew2, fmaf(e0.w,ew3, ebh))));
            ea[nt][1] = fmaf(e1.x,ew0, fmaf(e1.y,ew1, fmaf(e1.z,ew2, fmaf(e1.w,ew3, ebh))));
            ea[nt][2] = fmaf(e2.x,ew0, fmaf(e2.y,ew1, fmaf(e2.z,ew2, fmaf(e2.w,ew3, ebh))));
            ea[nt][3] = fmaf(e3.x,ew0, fmaf(e3.y,ew1, fmaf(e3.z,ew2, fmaf(e3.w,ew3, ebh))));
        }

        // QK MMA, columns 32..63
        #pragma unroll
        for (int kb = 0; kb < 64; kb += 8) {
            const float a0 = Qs[(w16 + g    )*QSTR + kb + tg    ];
            const float a1 = Qs[(w16 + g + 8)*QSTR + kb + tg    ];
            const float a2 = Qs[(w16 + g    )*QSTR + kb + tg + 4];
            const float a3 = Qs[(w16 + g + 8)*QSTR + kb + tg + 4];
            #pragma unroll
            for (int nt = 4; nt < 8; nt++) {
                const float b0 = Ks[(kb + tg    )*KSTR + nt*8 + g];
                const float b1 = Ks[(kb + tg + 4)*KSTR + nt*8 + g];
                mma8(s[nt], a0, a1, a2, a3, b0, b1);
            }
        }
        #pragma unroll
        for (int nt = 0; nt < 4; nt++)
            #pragma unroll
            for (int e = 0; e < 4; e++) s[nt + 4][e] += ea[nt][e];

        // online softmax
        float mt0 = -1e30f, mt1 = -1e30f;
        #pragma unroll
        for (int nt = 0; nt < 8; nt++) {
            mt0 = fmaxf(mt0, fmaxf(s[nt][0], s[nt][1]));
            mt1 = fmaxf(mt1, fmaxf(s[nt][2], s[nt][3]));
        }
        mt0 = fmaxf(mt0, __shfl_xor_sync(0xffffffffu, mt0, 1));
        mt0 = fmaxf(mt0, __shfl_xor_sync(0xffffffffu, mt0, 2));
        mt1 = fmaxf(mt1, __shfl_xor_sync(0xffffffffu, mt1, 1));
        mt1 = fmaxf(mt1, __shfl_xor_sync(0xffffffffu, mt1, 2));
        const float mn0 = fmaxf(m0, mt0), mn1 = fmaxf(m1, mt1);
        const float al0 = __expf(m0 - mn0), al1 = __expf(m1 - mn1);
        m0 = mn0; m1 = mn1;
        float rs0 = 0.f, rs1 = 0.f;
        #pragma unroll
        for (int nt = 0; nt < 8; nt++) {
            s[nt][0] = __expf(s[nt][0] - mn0); rs0 += s[nt][0];
            s[nt][1] = __expf(s[nt][1] - mn0); rs0 += s[nt][1];
            s[nt][2] = __expf(s[nt][2] - mn1); rs1 += s[nt][2];
            s[nt][3] = __expf(s[nt][3] - mn1); rs1 += s[nt][3];
        }
        rs0 += __shfl_xor_sync(0xffffffffu, rs0, 1);
        rs0 += __shfl_xor_sync(0xffffffffu, rs0, 2);
        rs1 += __shfl_xor_sync(0xffffffffu, rs1, 1);
        rs1 += __shfl_xor_sync(0xffffffffu, rs1, 2);
        l0 = l0*al0 + rs0; l1 = l1*al1 + rs1;
        #pragma unroll
        for (int dt = 0; dt < 8; dt++) {
            o[dt][0] *= al0; o[dt][1] *= al0;
            o[dt][2] *= al1; o[dt][3] *= al1;
        }

        // store P (tf32) — written & read by the same warp
        #pragma unroll
        for (int nt = 0; nt < 8; nt++) {
            float2 p0, p1;
            p0.x = f2tf(s[nt][0]); p0.y = f2tf(s[nt][1]);
            p1.x = f2tf(s[nt][2]); p1.y = f2tf(s[nt][3]);
            *(float2*)(Ps + (w16 + g    )*QSTR + nt*8 + 2*tg) = p0;
            *(float2*)(Ps + (w16 + g + 8)*QSTR + nt*8 + 2*tg) = p1;
        }
        __syncwarp();

        // O += P @ V
        #pragma unroll
        for (int kb = 0; kb < 64; kb += 8) {
            const float a0 = Ps[(w16 + g    )*QSTR + kb + tg    ];
            const float a1 = Ps[(w16 + g + 8)*QSTR + kb + tg    ];
            const float a2 = Ps[(w16 + g    )*QSTR + kb + tg + 4];
            const float a3 = Ps[(w16 + g + 8)*QSTR + kb + tg + 4];
            #pragma unroll
            for (int dt = 0; dt < 8; dt++) {
                const float b0 = Vs[(kb + tg    )*KSTR + dt*8 + g];
                const float b1 = Vs[(kb + tg + 4)*KSTR + dt*8 + g];
                mma8(o[dt], a0, a1, a2, a3, b0, b1);
            }
        }
    }

    const float inv0 = 1.f / l0, inv1 = 1.f / l1;
    float* op0 = ao + ((size_t)(bb*Nn + r0g    ))*Dd + hh*HDd;
    float* op1 = ao + ((size_t)(bb*Nn + r0g + 8))*Dd + hh*HDd;
    #pragma unroll
    for (int dt = 0; dt < 8; dt++) {
        const int dc = dt*8 + 2*tg;
        float2 o0, o1;
        o0.x = o[dt][0]*inv0; o0.y = o[dt][1]*inv0;
        o1.x = o[dt][2]*inv1; o1.y = o[dt][3]*inv1;
        *(float2*)(op0 + dc) = o0;
        *(float2*)(op1 + dc) = o1;
    }
}

// ---------------------------------------------------------------------------
// LayerNorm: one block (128 threads) per row of 512.
// ---------------------------------------------------------------------------
__global__ __launch_bounds__(128)
void ln_kernel(const float* __restrict__ h, const float* __restrict__ g,
               const float* __restrict__ b, float* __restrict__ out) {
    const int row = blockIdx.x;
    const int tid = threadIdx.x;
    const float4 x = *(const float4*)(h + (size_t)row*Dd + tid*4);
    float s  = x.x + x.y + x.z + x.w;
    float s2 = x.x*x.x + x.y*x.y + x.z*x.z + x.w*x.w;
    #pragma unroll
    for (int off = 16; off >= 1; off >>= 1) {
        s  += __shfl_xor_sync(0xffffffffu, s,  off);
        s2 += __shfl_xor_sync(0xffffffffu, s2, off);
    }
    __shared__ float ws[4], ws2[4];
    if ((tid & 31) == 0) { ws[tid>>5] = s; ws2[tid>>5] = s2; }
    __syncthreads();
    s  = ws[0] + ws[1] + ws[2] + ws[3];
    s2 = ws2[0] + ws2[1] + ws2[2] + ws2[3];
    const float mu  = s * (1.f/Dd);
    const float var = s2 * (1.f/Dd) - mu*mu;
    const float rstd = rsqrtf(var + 1e-5f);
    const float4 g4 = *(const float4*)(g + tid*4);
    const float4 b4 = *(const float4*)(b + tid*4);
    float4 r;
    r.x = (x.x - mu)*rstd*g4.x + b4.x;
    r.y = (x.y - mu)*rstd*g4.y + b4.y;
    r.z = (x.z - mu)*rstd*g4.z + b4.z;
    r.w = (x.w - mu)*rstd*g4.w + b4.w;
    *(float4*)(out + (size_t)row*Dd + tid*4) = r;
}

// ---------------------------------------------------------------------------
extern "C" void kernel_launch(void* const* d_in, const int* in_sizes, int n_in,
                              void* d_out, int out_size) {
    (void)in_sizes; (void)n_in; (void)out_size;
    const float* x    = (const float*)d_in[0];
    const float* edges= (const float*)d_in[1];
    const float* in_w = (const float*)d_in[2];
    const float* in_b = (const float*)d_in[3];
    const float* qw   = (const float*)d_in[4];
    const float* qb   = (const float*)d_in[5];
    const float* kw   = (const float*)d_in[6];
    const float* kb   = (const float*)d_in[7];
    const float* vw   = (const float*)d_in[8];
    const float* vb   = (const float*)d_in[9];
    const float* ow   = (const float*)d_in[10];
    const float* ob   = (const float*)d_in[11];
    const float* ew   = (const float*)d_in[12];
    const float* eb   = (const float*)d_in[13];
    const float* ln_g = (const float*)d_in[14];
    const float* ln_b = (const float*)d_in[15];
    float* out = (float*)d_out;

    float *h, *q, *k, *v, *ao;
    cudaGetSymbolAddress((void**)&h,  g_h);
    cudaGetSymbolAddress((void**)&q,  g_q);
    cudaGetSymbolAddress((void**)&k,  g_k);
    cudaGetSymbolAddress((void**)&v,  g_v);
    cudaGetSymbolAddress((void**)&ao, g_ao);

    cudaFuncSetAttribute(gemm_tf32<false>, cudaFuncAttributeMaxDynamicSharedMemorySize, GEMM_SMEM);
    cudaFuncSetAttribute(gemm_tf32<true>,  cudaFuncAttributeMaxDynamicSharedMemorySize, GEMM_SMEM);
    cudaFuncSetAttribute(qkv_tf32,         cudaFuncAttributeMaxDynamicSharedMemorySize, GEMM_SMEM);
    cudaFuncSetAttribute(attn_tf32,        cudaFuncAttributeMaxDynamicSharedMemorySize, ATTN_SMEM);

    dim3 gg(BNROWS/128, Dd/64);            // (32, 8)
    dim3 gq(BNROWS/128, Dd/64, 3);         // fused QKV
    dim3 ag(Hh, Nn/128, Bsz);              // (8, 8, 4)

    // h = x @ in_w + in_b
    gemm_tf32<false><<<gg, 256, GEMM_SMEM>>>(x, in_w, in_b, nullptr, h, IND, Dd);

    for (int l = 0; l < Ll; l++) {
        const size_t wo = (size_t)l*Dd*Dd;
        qkv_tf32<<<gq, 256, GEMM_SMEM>>>(h, qw + wo, qb + l*Dd, kw + wo, kb + l*Dd,
                                         vw + wo, vb + l*Dd, q, k, v);
        attn_tf32<<<ag, 256, ATTN_SMEM>>>(q, k, v, edges,
                                          ew + l*Ee*Hh, eb + l*Hh, ao);
        // h = h + ao @ ow + ob
        gemm_tf32<true><<<gg, 256, GEMM_SMEM>>>(ao, ow + wo, ob + l*Dd, h, h, Dd, Dd);
    }

    ln_kernel<<<BNROWS, 128>>>(h, ln_g, ln_b, out);
}

// round 8
// speedup vs baseline: 1.7158x; 1.7158x over previous
#include <cuda_runtime.h>
#include <cuda_fp16.h>
#include <math.h>
#include <stdint.h>

#define Bsz 4
#define Nn 1024
#define IND 128
#define Dd 512
#define Hh 8
#define HDd 64
#define Ee 4
#define Ll 3
#define BNROWS (Bsz*Nn)   // 4096

// Scratch (device globals: no cudaMalloc allowed)
__device__ float g_h [BNROWS*Dd];
__device__ float g_q [BNROWS*Dd];
__device__ float g_k [BNROWS*Dd];
__device__ float g_v [BNROWS*Dd];
__device__ float g_ao[BNROWS*Dd];

// ---------------------------------------------------------------------------
// fp16 helpers
// ---------------------------------------------------------------------------
__device__ __forceinline__ uint32_t pk(float x, float y) {
    __half2 h = __floats2half2_rn(x, y);
    return *reinterpret_cast<uint32_t*>(&h);
}

// D = A(16x16) * B(16x8) + C ; fp16 in, fp32 accumulate.
__device__ __forceinline__ void mma16(float* c, uint32_t a0, uint32_t a1,
                                      uint32_t a2, uint32_t a3,
                                      uint32_t b0, uint32_t b1) {
    asm volatile(
        "mma.sync.aligned.m16n8k16.row.col.f32.f16.f16.f32 "
        "{%0,%1,%2,%3},{%4,%5,%6,%7},{%8,%9},{%0,%1,%2,%3};"
        : "+f"(c[0]), "+f"(c[1]), "+f"(c[2]), "+f"(c[3])
        : "r"(a0), "r"(a1), "r"(a2), "r"(a3), "r"(b0), "r"(b1));
}

// ---------------------------------------------------------------------------
// fp16 GEMM: C[M x 512] = A[M x K] @ W[K x 512] + bias (+ res)
// CTA tile 128x64, BK=32 (16 k-pairs), double-buffered smem.
// 8 warps (4x2), warp tile 32x32: 2 mt x 4 nt x 2 ksteps of m16n8k16.
// Smem holds half2-packed words: As2[128][20], Bs2[64][20] (k-pairs contiguous).
// ---------------------------------------------------------------------------
#define GA_STR2 20
#define GB_STR2 20
#define GA_SZ (128*GA_STR2)
#define GB_SZ (64*GB_STR2)
#define GEMM_SMEM ((2*GA_SZ + 2*GB_SZ)*4)   // 30720 B

template<bool RES>
__device__ __forceinline__
void gemm_body(const float* __restrict__ A, const float* __restrict__ W,
               const float* __restrict__ bias, const float* __restrict__ res,
               float* __restrict__ C, int K, int bm, int bn) {
    extern __shared__ uint32_t smg[];
    uint32_t* As = smg;               // [2][GA_SZ]
    uint32_t* Bs = smg + 2*GA_SZ;     // [2][GB_SZ]

    const int tid  = threadIdx.x;
    const int lane = tid & 31;
    const int warp = tid >> 5;
    const int wm   = warp & 3;
    const int wn   = warp >> 2;
    const int g    = lane >> 2;
    const int tg   = lane & 3;

    const int ar  = tid >> 3;           // 0..31 (A rows ar + 32p)
    const int ac  = (tid & 7) << 2;     // 0..28
    const int ac2 = ac >> 1;            // pair index (even)
    const int bnr = tid & 63;           // B row (= output col n)
    const int bkq = (tid >> 6) << 3;    // 8 k-values per thread
    const int bk2 = bkq >> 1;           // 0,4,8,12

    float4 ra[4];
    float  rb[8];

    auto LD = [&](int k0) {
        #pragma unroll
        for (int p = 0; p < 4; p++)
            ra[p] = *(const float4*)(A + (size_t)(bm + ar + 32*p)*K + k0 + ac);
        const float* wp = W + (size_t)(k0 + bkq)*Dd + bn + bnr;
        #pragma unroll
        for (int i = 0; i < 8; i++) rb[i] = wp[(size_t)i * Dd];
    };
    auto ST = [&](int st) {
        uint32_t* as = As + st*GA_SZ;
        uint32_t* bs = Bs + st*GB_SZ;
        #pragma unroll
        for (int p = 0; p < 4; p++) {
            uint2 t;
            t.x = pk(ra[p].x, ra[p].y);
            t.y = pk(ra[p].z, ra[p].w);
            *(uint2*)(as + (ar + 32*p)*GA_STR2 + ac2) = t;
        }
        uint4 b4;
        b4.x = pk(rb[0], rb[1]); b4.y = pk(rb[2], rb[3]);
        b4.z = pk(rb[4], rb[5]); b4.w = pk(rb[6], rb[7]);
        *(uint4*)(bs + bnr*GB_STR2 + bk2) = b4;
    };

    float acc[2][4][4];
    #pragma unroll
    for (int mt = 0; mt < 2; mt++)
        #pragma unroll
        for (int nt = 0; nt < 4; nt++)
            #pragma unroll
            for (int e = 0; e < 4; e++) acc[mt][nt][e] = 0.f;

    LD(0); ST(0); __syncthreads();

    const int T = K >> 5;
    for (int t = 0; t < T; t++) {
        if (t + 1 < T) LD((t + 1) << 5);

        const uint32_t* as = As + (t & 1)*GA_SZ;
        const uint32_t* bs = Bs + (t & 1)*GB_SZ;
        #pragma unroll
        for (int ks = 0; ks < 2; ks++) {
            const int k2 = ks * 8;
            uint32_t a[2][4];
            #pragma unroll
            for (int mt = 0; mt < 2; mt++) {
                const int r = wm*32 + mt*16;
                a[mt][0] = as[(r + g    )*GA_STR2 + k2 + tg    ];
                a[mt][1] = as[(r + g + 8)*GA_STR2 + k2 + tg    ];
                a[mt][2] = as[(r + g    )*GA_STR2 + k2 + tg + 4];
                a[mt][3] = as[(r + g + 8)*GA_STR2 + k2 + tg + 4];
            }
            uint32_t b[4][2];
            #pragma unroll
            for (int nt = 0; nt < 4; nt++) {
                const int cc = wn*32 + nt*8 + g;
                b[nt][0] = bs[cc*GB_STR2 + k2 + tg    ];
                b[nt][1] = bs[cc*GB_STR2 + k2 + tg + 4];
            }
            #pragma unroll
            for (int mt = 0; mt < 2; mt++)
                #pragma unroll
                for (int nt = 0; nt < 4; nt++)
                    mma16(acc[mt][nt], a[mt][0], a[mt][1], a[mt][2], a[mt][3],
                          b[nt][0], b[nt][1]);
        }

        if (t + 1 < T) {
            ST((t + 1) & 1);
            __syncthreads();
        }
    }

    #pragma unroll
    for (int mt = 0; mt < 2; mt++) {
        const int r0 = bm + wm*32 + mt*16 + g;
        #pragma unroll
        for (int nt = 0; nt < 4; nt++) {
            const int cc = bn + wn*32 + nt*8 + 2*tg;
            const float b0 = bias[cc], b1 = bias[cc + 1];
            float2 o0, o1;
            o0.x = acc[mt][nt][0] + b0; o0.y = acc[mt][nt][1] + b1;
            o1.x = acc[mt][nt][2] + b0; o1.y = acc[mt][nt][3] + b1;
            const size_t off0 = (size_t)r0*Dd + cc;
            const size_t off1 = (size_t)(r0 + 8)*Dd + cc;
            if (RES) {
                float2 p0 = *(const float2*)(res + off0);
                float2 p1 = *(const float2*)(res + off1);
                o0.x += p0.x; o0.y += p0.y; o1.x += p1.x; o1.y += p1.y;
            }
            *(float2*)(C + off0) = o0;
            *(float2*)(C + off1) = o1;
        }
    }
}

template<bool RES>
__global__ __launch_bounds__(256)
void gemm_h(const float* __restrict__ A, const float* __restrict__ W,
            const float* __restrict__ bias, const float* __restrict__ res,
            float* __restrict__ C, int K) {
    gemm_body<RES>(A, W, bias, res, C, K, blockIdx.x * 128, blockIdx.y * 64);
}

__global__ __launch_bounds__(256)
void qkv_h(const float* __restrict__ h,
           const float* __restrict__ qw, const float* __restrict__ qb,
           const float* __restrict__ kw, const float* __restrict__ kb,
           const float* __restrict__ vw, const float* __restrict__ vb,
           float* __restrict__ q, float* __restrict__ k, float* __restrict__ v) {
    const int z = blockIdx.z;
    const float* W  = (z == 0) ? qw : (z == 1) ? kw : vw;
    const float* Bi = (z == 0) ? qb : (z == 1) ? kb : vb;
    float*       C  = (z == 0) ? q  : (z == 1) ? k  : v;
    gemm_body<false>(h, W, Bi, nullptr, C, Dd, blockIdx.x * 128, blockIdx.y * 64);
}

// ---------------------------------------------------------------------------
// fp16 flash attention with edge bias (R3 dataflow).
// CTA = (head, 128-row i-tile, batch). 8 warps, warp w owns rows w*16..+15.
// Smem (uint32 = half2 words, stride 36):
//   Qs2[128][36] (i-major, d-pairs), Ks2[64][36] (j-major, d-pairs),
//   Vs2[64][36] (d-major, j-pairs), Ps2[128][36] (i-major, j-pairs).
// ---------------------------------------------------------------------------
#define A_STR 36
#define ATTN_SMEM ((128*A_STR + 64*A_STR + 64*A_STR + 128*A_STR)*4)  // 55296 B

__global__ __launch_bounds__(256)
void attn_h(const float* __restrict__ q, const float* __restrict__ k,
            const float* __restrict__ v, const float* __restrict__ edges,
            const float* __restrict__ ew, const float* __restrict__ eb,
            float* __restrict__ ao) {
    extern __shared__ uint32_t sma[];
    uint32_t* Qs = sma;                   // [128][36]
    uint32_t* Ks = Qs + 128*A_STR;        // [64][36]
    uint32_t* Vs = Ks + 64*A_STR;         // [64][36]
    uint32_t* Ps = Vs + 64*A_STR;         // [128][36]

    const int tid  = threadIdx.x;
    const int lane = tid & 31;
    const int w    = tid >> 5;
    const int g    = lane >> 2;
    const int tg   = lane & 3;
    const int hh   = blockIdx.x;
    const int i0   = blockIdx.y * 128;
    const int bb   = blockIdx.z;
    const int w16  = w * 16;

    const float ew0 = ew[hh], ew1 = ew[Hh + hh];
    const float ew2 = ew[2*Hh + hh], ew3 = ew[3*Hh + hh];
    const float ebh = eb[hh];

    const int lr = tid >> 2;             // 0..63
    const int lc = (tid & 3) << 2;       // 0,4,8,12
    const int td = tid & 63;             // V staging: d
    const int tj = tid >> 6;             // V staging: j-pair block

    // Load Q (scaled 0.125 -> fp16 pairs): rows lr, lr+64
    #pragma unroll
    for (int rr = 0; rr < 2; rr++) {
        const int r = lr + rr*64;
        const float* qp = q + ((size_t)(bb*Nn + i0 + r))*Dd + hh*HDd;
        #pragma unroll
        for (int p = 0; p < 4; p++) {
            const int d = lc + p*16;
            float4 a = *(const float4*)(qp + d);
            uint2 t;
            t.x = pk(a.x * 0.125f, a.y * 0.125f);
            t.y = pk(a.z * 0.125f, a.w * 0.125f);
            *(uint2*)(Qs + r*A_STR + (d >> 1)) = t;
        }
    }

    float o[8][4];
    #pragma unroll
    for (int dt = 0; dt < 8; dt++)
        #pragma unroll
        for (int e = 0; e < 4; e++) o[dt][e] = 0.f;
    float m0 = -1e30f, m1 = -1e30f, l0 = 0.f, l1 = 0.f;

    const int    r0g = i0 + w16 + g;
    const size_t eb0 = ((size_t)bb*Nn + r0g)*Nn;
    const size_t eb1 = eb0 + 8*(size_t)Nn;

    for (int j0 = 0; j0 < Nn; j0 += 64) {
        __syncthreads();   // previous tile's Ks/Vs reads done

        // stage K (j-major, d-pairs)
        {
            const float* kp = k + ((size_t)(bb*Nn + j0 + lr))*Dd + hh*HDd;
            #pragma unroll
            for (int p = 0; p < 4; p++) {
                const int d = lc + p*16;
                float4 kv = *(const float4*)(kp + d);
                uint2 t;
                t.x = pk(kv.x, kv.y);
                t.y = pk(kv.z, kv.w);
                *(uint2*)(Ks + lr*A_STR + (d >> 1)) = t;
            }
        }
        // stage V transposed (d-major, j-pairs)
        {
            const float* vp = v + ((size_t)(bb*Nn + j0))*Dd + hh*HDd + td;
            #pragma unroll
            for (int pp = 0; pp < 8; pp++) {
                const int p = tj*8 + pp;          // j-pair 0..31
                float v0 = vp[(size_t)(2*p    )*Dd];
                float v1 = vp[(size_t)(2*p + 1)*Dd];
                Vs[td*A_STR + p] = pk(v0, v1);
            }
        }

        // edge bias -> S accumulator init (fp32)
        float s[8][4];
        #pragma unroll
        for (int nt = 0; nt < 8; nt++) {
            const int jc = j0 + nt*8 + 2*tg;
            float4 e0 = *(const float4*)(edges + (eb0 + jc    )*Ee);
            float4 e1 = *(const float4*)(edges + (eb0 + jc + 1)*Ee);
            float4 e2 = *(const float4*)(edges + (eb1 + jc    )*Ee);
            float4 e3 = *(const float4*)(edges + (eb1 + jc + 1)*Ee);
            s[nt][0] = fmaf(e0.x,ew0, fmaf(e0.y,ew1, fmaf(e0.z,ew2, fmaf(e0.w,ew3, ebh))));
            s[nt][1] = fmaf(e1.x,ew0, fmaf(e1.y,ew1, fmaf(e1.z,ew2, fmaf(e1.w,ew3, ebh))));
            s[nt][2] = fmaf(e2.x,ew0, fmaf(e2.y,ew1, fmaf(e2.z,ew2, fmaf(e2.w,ew3, ebh))));
            s[nt][3] = fmaf(e3.x,ew0, fmaf(e3.y,ew1, fmaf(e3.z,ew2, fmaf(e3.w,ew3, ebh))));
        }
        __syncthreads();   // Ks/Vs ready

        // S += Q K^T : 4 ksteps of 16 over d=64
        #pragma unroll
        for (int d2 = 0; d2 < 32; d2 += 8) {
            const uint32_t a0 = Qs[(w16 + g    )*A_STR + d2 + tg    ];
            const uint32_t a1 = Qs[(w16 + g + 8)*A_STR + d2 + tg    ];
            const uint32_t a2 = Qs[(w16 + g    )*A_STR + d2 + tg + 4];
            const uint32_t a3 = Qs[(w16 + g + 8)*A_STR + d2 + tg + 4];
            #pragma unroll
            for (int nt = 0; nt < 8; nt++) {
                const uint32_t b0 = Ks[(nt*8 + g)*A_STR + d2 + tg    ];
                const uint32_t b1 = Ks[(nt*8 + g)*A_STR + d2 + tg + 4];
                mma16(s[nt], a0, a1, a2, a3, b0, b1);
            }
        }

        // online softmax (rows r0g, r0g+8)
        float mt0 = -1e30f, mt1 = -1e30f;
        #pragma unroll
        for (int nt = 0; nt < 8; nt++) {
            mt0 = fmaxf(mt0, fmaxf(s[nt][0], s[nt][1]));
            mt1 = fmaxf(mt1, fmaxf(s[nt][2], s[nt][3]));
        }
        mt0 = fmaxf(mt0, __shfl_xor_sync(0xffffffffu, mt0, 1));
        mt0 = fmaxf(mt0, __shfl_xor_sync(0xffffffffu, mt0, 2));
        mt1 = fmaxf(mt1, __shfl_xor_sync(0xffffffffu, mt1, 1));
        mt1 = fmaxf(mt1, __shfl_xor_sync(0xffffffffu, mt1, 2));
        const float mn0 = fmaxf(m0, mt0), mn1 = fmaxf(m1, mt1);
        const float al0 = __expf(m0 - mn0), al1 = __expf(m1 - mn1);
        m0 = mn0; m1 = mn1;
        float rs0 = 0.f, rs1 = 0.f;
        #pragma unroll
        for (int nt = 0; nt < 8; nt++) {
            s[nt][0] = __expf(s[nt][0] - mn0); rs0 += s[nt][0];
            s[nt][1] = __expf(s[nt][1] - mn0); rs0 += s[nt][1];
            s[nt][2] = __expf(s[nt][2] - mn1); rs1 += s[nt][2];
            s[nt][3] = __expf(s[nt][3] - mn1); rs1 += s[nt][3];
        }
        rs0 += __shfl_xor_sync(0xffffffffu, rs0, 1);
        rs0 += __shfl_xor_sync(0xffffffffu, rs0, 2);
        rs1 += __shfl_xor_sync(0xffffffffu, rs1, 1);
        rs1 += __shfl_xor_sync(0xffffffffu, rs1, 2);
        l0 = l0*al0 + rs0; l1 = l1*al1 + rs1;
        #pragma unroll
        for (int dt = 0; dt < 8; dt++) {
            o[dt][0] *= al0; o[dt][1] *= al0;
            o[dt][2] *= al1; o[dt][3] *= al1;
        }

        // store P (fp16 pairs) — written & read by the same warp
        #pragma unroll
        for (int nt = 0; nt < 8; nt++) {
            Ps[(w16 + g    )*A_STR + nt*4 + tg] = pk(s[nt][0], s[nt][1]);
            Ps[(w16 + g + 8)*A_STR + nt*4 + tg] = pk(s[nt][2], s[nt][3]);
        }
        __syncwarp();

        // O += P @ V : 4 ksteps of 16 over the full j-tile of 64
        #pragma unroll
        for (int j2 = 0; j2 < 32; j2 += 8) {
            const uint32_t a0 = Ps[(w16 + g    )*A_STR + j2 + tg    ];
            const uint32_t a1 = Ps[(w16 + g + 8)*A_STR + j2 + tg    ];
            const uint32_t a2 = Ps[(w16 + g    )*A_STR + j2 + tg + 4];
            const uint32_t a3 = Ps[(w16 + g + 8)*A_STR + j2 + tg + 4];
            #pragma unroll
            for (int dt = 0; dt < 8; dt++) {
                const uint32_t b0 = Vs[(dt*8 + g)*A_STR + j2 + tg    ];
                const uint32_t b1 = Vs[(dt*8 + g)*A_STR + j2 + tg + 4];
                mma16(o[dt], a0, a1, a2, a3, b0, b1);
            }
        }
    }

    const float inv0 = 1.f / l0, inv1 = 1.f / l1;
    float* op0 = ao + ((size_t)(bb*Nn + r0g    ))*Dd + hh*HDd;
    float* op1 = ao + ((size_t)(bb*Nn + r0g + 8))*Dd + hh*HDd;
    #pragma unroll
    for (int dt = 0; dt < 8; dt++) {
        const int dc = dt*8 + 2*tg;
        float2 o0, o1;
        o0.x = o[dt][0]*inv0; o0.y = o[dt][1]*inv0;
        o1.x = o[dt][2]*inv1; o1.y = o[dt][3]*inv1;
        *(float2*)(op0 + dc) = o0;
        *(float2*)(op1 + dc) = o1;
    }
}

// ---------------------------------------------------------------------------
// LayerNorm: one block (128 threads) per row of 512.
// ---------------------------------------------------------------------------
__global__ __launch_bounds__(128)
void ln_kernel(const float* __restrict__ h, const float* __restrict__ g,
               const float* __restrict__ b, float* __restrict__ out) {
    const int row = blockIdx.x;
    const int tid = threadIdx.x;
    const float4 x = *(const float4*)(h + (size_t)row*Dd + tid*4);
    float s  = x.x + x.y + x.z + x.w;
    float s2 = x.x*x.x + x.y*x.y + x.z*x.z + x.w*x.w;
    #pragma unroll
    for (int off = 16; off >= 1; off >>= 1) {
        s  += __shfl_xor_sync(0xffffffffu, s,  off);
        s2 += __shfl_xor_sync(0xffffffffu, s2, off);
    }
    __shared__ float ws[4], ws2[4];
    if ((tid & 31) == 0) { ws[tid>>5] = s; ws2[tid>>5] = s2; }
    __syncthreads();
    s  = ws[0] + ws[1] + ws[2] + ws[3];
    s2 = ws2[0] + ws2[1] + ws2[2] + ws2[3];
    const float mu  = s * (1.f/Dd);
    const float var = s2 * (1.f/Dd) - mu*mu;
    const float rstd = rsqrtf(var + 1e-5f);
    const float4 g4 = *(const float4*)(g + tid*4);
    const float4 b4 = *(const float4*)(b + tid*4);
    float4 r;
    r.x = (x.x - mu)*rstd*g4.x + b4.x;
    r.y = (x.y - mu)*rstd*g4.y + b4.y;
    r.z = (x.z - mu)*rstd*g4.z + b4.z;
    r.w = (x.w - mu)*rstd*g4.w + b4.w;
    *(float4*)(out + (size_t)row*Dd + tid*4) = r;
}

// ---------------------------------------------------------------------------
extern "C" void kernel_launch(void* const* d_in, const int* in_sizes, int n_in,
                              void* d_out, int out_size) {
    (void)in_sizes; (void)n_in; (void)out_size;
    const float* x    = (const float*)d_in[0];
    const float* edges= (const float*)d_in[1];
    const float* in_w = (const float*)d_in[2];
    const float* in_b = (const float*)d_in[3];
    const float* qw   = (const float*)d_in[4];
    const float* qb   = (const float*)d_in[5];
    const float* kw   = (const float*)d_in[6];
    const float* kb   = (const float*)d_in[7];
    const float* vw   = (const float*)d_in[8];
    const float* vb   = (const float*)d_in[9];
    const float* ow   = (const float*)d_in[10];
    const float* ob   = (const float*)d_in[11];
    const float* ew   = (const float*)d_in[12];
    const float* eb   = (const float*)d_in[13];
    const float* ln_g = (const float*)d_in[14];
    const float* ln_b = (const float*)d_in[15];
    float* out = (float*)d_out;

    float *h, *q, *k, *v, *ao;
    cudaGetSymbolAddress((void**)&h,  g_h);
    cudaGetSymbolAddress((void**)&q,  g_q);
    cudaGetSymbolAddress((void**)&k,  g_k);
    cudaGetSymbolAddress((void**)&v,  g_v);
    cudaGetSymbolAddress((void**)&ao, g_ao);

    cudaFuncSetAttribute(gemm_h<false>, cudaFuncAttributeMaxDynamicSharedMemorySize, GEMM_SMEM);
    cudaFuncSetAttribute(gemm_h<true>,  cudaFuncAttributeMaxDynamicSharedMemorySize, GEMM_SMEM);
    cudaFuncSetAttribute(qkv_h,         cudaFuncAttributeMaxDynamicSharedMemorySize, GEMM_SMEM);
    cudaFuncSetAttribute(attn_h,        cudaFuncAttributeMaxDynamicSharedMemorySize, ATTN_SMEM);

    dim3 gg(BNROWS/128, Dd/64);            // (32, 8)
    dim3 gq(BNROWS/128, Dd/64, 3);         // fused QKV
    dim3 ag(Hh, Nn/128, Bsz);              // (8, 8, 4)

    // h = x @ in_w + in_b
    gemm_h<false><<<gg, 256, GEMM_SMEM>>>(x, in_w, in_b, nullptr, h, IND);

    for (int l = 0; l < Ll; l++) {
        const size_t wo = (size_t)l*Dd*Dd;
        qkv_h<<<gq, 256, GEMM_SMEM>>>(h, qw + wo, qb + l*Dd, kw + wo, kb + l*Dd,
                                      vw + wo, vb + l*Dd, q, k, v);
        attn_h<<<ag, 256, ATTN_SMEM>>>(q, k, v, edges,
                                       ew + l*Ee*Hh, eb + l*Hh, ao);
        // h = h + ao @ ow + ob
        gemm_h<true><<<gg, 256, GEMM_SMEM>>>(ao, ow + wo, ob + l*Dd, h, h, Dd);
    }

    ln_kernel<<<BNROWS, 128>>>(h, ln_g, ln_b, out);
}

// round 11
// speedup vs baseline: 1.9041x; 1.1098x over previous
#include <cuda_runtime.h>
#include <cuda_fp16.h>
#include <math.h>
#include <stdint.h>

#define Bsz 4
#define Nn 1024
#define IND 128
#define Dd 512
#define Hh 8
#define HDd 64
#define Ee 4
#define Ll 3
#define BNROWS (Bsz*Nn)   // 4096

// ---------------------------------------------------------------------------
// Scratch (device globals: no cudaMalloc allowed)
// ---------------------------------------------------------------------------
__device__ float  g_h   [BNROWS*Dd];
__device__ __half g_h16 [BNROWS*Dd];
__device__ __half g_x16 [BNROWS*IND];
__device__ __half g_q16 [BNROWS*Dd];
__device__ __half g_k16 [BNROWS*Dd];
__device__ __half g_v16 [BNROWS*Dd];
__device__ __half g_ao16[BNROWS*Dd];
// transposed fp16 weights: in_w^T [512][128], then per (l, {q,k,v,o}): [512][512]
__device__ __half g_w16t[512*128 + 12*512*512];
// per-layer edge bias: [L][B][H][N][N] fp32
__device__ float g_bias32[(size_t)Ll*Bsz*Hh*Nn*Nn];

#define WOFF_L(l, m) (512*128 + ((size_t)((l)*4 + (m)))*512*512)

// ---------------------------------------------------------------------------
// helpers
// ---------------------------------------------------------------------------
__device__ __forceinline__ uint32_t pk(float x, float y) {
    __half2 h = __floats2half2_rn(x, y);
    return *reinterpret_cast<uint32_t*>(&h);
}

__device__ __forceinline__ uint32_t smem_u32(const void* p) {
    uint32_t a;
    asm("{ .reg .u64 t; cvta.to.shared.u64 t, %1; cvt.u32.u64 %0, t; }"
        : "=r"(a) : "l"(p));
    return a;
}

__device__ __forceinline__ void mma16(float* c, uint32_t a0, uint32_t a1,
                                      uint32_t a2, uint32_t a3,
                                      uint32_t b0, uint32_t b1) {
    asm volatile(
        "mma.sync.aligned.m16n8k16.row.col.f32.f16.f16.f32 "
        "{%0,%1,%2,%3},{%4,%5,%6,%7},{%8,%9},{%0,%1,%2,%3};"
        : "+f"(c[0]), "+f"(c[1]), "+f"(c[2]), "+f"(c[3])
        : "r"(a0), "r"(a1), "r"(a2), "r"(a3), "r"(b0), "r"(b1));
}

#define LDMX4(r0,r1,r2,r3,addr) \
    asm volatile("ldmatrix.sync.aligned.m8n8.x4.shared.b16 {%0,%1,%2,%3}, [%4];" \
                 : "=r"(r0),"=r"(r1),"=r"(r2),"=r"(r3) : "r"(addr))
#define LDMX4T(r0,r1,r2,r3,addr) \
    asm volatile("ldmatrix.sync.aligned.m8n8.x4.trans.shared.b16 {%0,%1,%2,%3}, [%4];" \
                 : "=r"(r0),"=r"(r1),"=r"(r2),"=r"(r3) : "r"(addr))

__device__ __forceinline__ void cpa16(uint32_t dst, const void* src) {
    asm volatile("cp.async.cg.shared.global [%0], [%1], 16;" :: "r"(dst), "l"(src));
}
#define CPA_COMMIT() asm volatile("cp.async.commit_group;")
#define CPA_WAIT1()  asm volatile("cp.async.wait_group 1;")
#define CPA_WAIT0()  asm volatile("cp.async.wait_group 0;")

// ---------------------------------------------------------------------------
// Pre-pass 1: weight convert + transpose -> fp16 [n][k]
// ---------------------------------------------------------------------------
__global__ void wtrans(const float* __restrict__ in_w, const float* __restrict__ qw,
                       const float* __restrict__ kw, const float* __restrict__ vw,
                       const float* __restrict__ ow, __half* __restrict__ w16t) {
    const int z = blockIdx.z;
    const float* src; int K; size_t doff;
    if (z == 0) { src = in_w; K = IND; doff = 0; }
    else {
        const int li = (z - 1) >> 2, m = (z - 1) & 3;
        const float* base = (m == 0) ? qw : (m == 1) ? kw : (m == 2) ? vw : ow;
        src = base + (size_t)li * Dd * Dd;
        K = Dd; doff = 512*128 + (size_t)(z - 1) * 512 * 512;
    }
    const int k0 = blockIdx.x * 32, n0 = blockIdx.y * 32;
    if (k0 >= K) return;
    __shared__ float tile[32][33];
    const int tx = threadIdx.x, ty = threadIdx.y;
    #pragma unroll
    for (int i = 0; i < 4; i++)
        tile[ty + i*8][tx] = src[(size_t)(k0 + ty + i*8) * Dd + n0 + tx];
    __syncthreads();
    #pragma unroll
    for (int i = 0; i < 4; i++)
        w16t[doff + (size_t)(n0 + ty + i*8) * K + k0 + tx] =
            __float2half(tile[tx][ty + i*8]);
}

// Pre-pass 2: x -> fp16
__global__ void cvt_x16(const float* __restrict__ x, __half* __restrict__ x16) {
    const int i = (blockIdx.x * 256 + threadIdx.x) * 8;
    float4 a = *(const float4*)(x + i);
    float4 b = *(const float4*)(x + i + 4);
    uint4 u;
    u.x = pk(a.x, a.y); u.y = pk(a.z, a.w);
    u.z = pk(b.x, b.y); u.w = pk(b.z, b.w);
    *(uint4*)(x16 + i) = u;
}

// Pre-pass 3: edge bias for all layers (fp32): bias32[l][b][h][i][j]
__global__ void edgeproj(const float* __restrict__ edges, const float* __restrict__ ew,
                         const float* __restrict__ eb, float* __restrict__ bias32) {
    const int t  = blockIdx.x * 256 + threadIdx.x;   // 524288 threads
    const int jo = t & 127;
    const int i  = (t >> 7) & 1023;
    const int b  = t >> 17;
    const float* ep = edges + (((size_t)b * Nn + i) * Nn + (size_t)jo * 8) * Ee;
    float e[8][4];
    #pragma unroll
    for (int p = 0; p < 8; p++) {
        float4 v = *(const float4*)(ep + p * 4);
        e[p][0] = v.x; e[p][1] = v.y; e[p][2] = v.z; e[p][3] = v.w;
    }
    #pragma unroll
    for (int l = 0; l < Ll; l++) {
        #pragma unroll
        for (int h = 0; h < Hh; h++) {
            const float w0 = ew[l*32 + h],      w1 = ew[l*32 + 8 + h];
            const float w2 = ew[l*32 + 16 + h], w3 = ew[l*32 + 24 + h];
            const float bb = eb[l*8 + h];
            float* dst = bias32 + (((size_t)((l*Bsz + b)*Hh + h)) << 20)
                                + (size_t)i * Nn + jo * 8;
            float4 u0, u1;
            u0.x = fmaf(e[0][0],w0, fmaf(e[0][1],w1, fmaf(e[0][2],w2, fmaf(e[0][3],w3, bb))));
            u0.y = fmaf(e[1][0],w0, fmaf(e[1][1],w1, fmaf(e[1][2],w2, fmaf(e[1][3],w3, bb))));
            u0.z = fmaf(e[2][0],w0, fmaf(e[2][1],w1, fmaf(e[2][2],w2, fmaf(e[2][3],w3, bb))));
            u0.w = fmaf(e[3][0],w0, fmaf(e[3][1],w1, fmaf(e[3][2],w2, fmaf(e[3][3],w3, bb))));
            u1.x = fmaf(e[4][0],w0, fmaf(e[4][1],w1, fmaf(e[4][2],w2, fmaf(e[4][3],w3, bb))));
            u1.y = fmaf(e[5][0],w0, fmaf(e[5][1],w1, fmaf(e[5][2],w2, fmaf(e[5][3],w3, bb))));
            u1.z = fmaf(e[6][0],w0, fmaf(e[6][1],w1, fmaf(e[6][2],w2, fmaf(e[6][3],w3, bb))));
            u1.w = fmaf(e[7][0],w0, fmaf(e[7][1],w1, fmaf(e[7][2],w2, fmaf(e[7][3],w3, bb))));
            *(float4*)(dst)     = u0;
            *(float4*)(dst + 4) = u1;
        }
    }
}

// ---------------------------------------------------------------------------
// fp16 GEMM: C[M x 512] = A16[M x K] @ W16T^T + bias (+ res)
// CTA 128x64, BK=32, 3-stage cp.async, ldmatrix fragments.
// RACE FIX: last tile must drain with wait_group 0 (wait_group 1 left the
// final group pending -> stale smem on the last k-tile; R8/R9 failures).
// ---------------------------------------------------------------------------
#define GASTR 40
#define GA_HSZ (128*GASTR)        // 5120 halfs
#define GB_HSZ (64*GASTR)         // 2560 halfs
#define GSTG_H (GA_HSZ + GB_HSZ)  // 7680 halfs / stage
#define GEMM_SMEM (3*GSTG_H*2)    // 46080 B

template<bool RES, bool WF32>
__device__ __forceinline__
void gemm16_body(const __half* __restrict__ A16, const __half* __restrict__ WT,
                 const float* __restrict__ bias, const float* __restrict__ res,
                 float* __restrict__ C32, __half* __restrict__ C16,
                 float scale, int K, int bm, int bn) {
    extern __shared__ __half smh[];
    const uint32_t sb = smem_u32(smh);
    const int tid  = threadIdx.x;
    const int lane = tid & 31;
    const int warp = tid >> 5;
    const int wm   = warp & 3;
    const int wn   = warp >> 2;
    const int g    = lane >> 2;
    const int tg   = lane & 3;

    auto issue = [&](int t) {
        const int k0 = t << 5;
        const uint32_t ab = sb + ((t % 3) * GSTG_H) * 2;
        const uint32_t bb = ab + GA_HSZ * 2;
        #pragma unroll
        for (int c = tid; c < 512; c += 256) {
            const int row = c >> 2, cc = c & 3;
            cpa16(ab + (row*GASTR + cc*8)*2,
                  A16 + (size_t)(bm + row)*K + k0 + cc*8);
        }
        { const int row = tid >> 2, cc = tid & 3;
          cpa16(bb + (row*GASTR + cc*8)*2,
                WT + (size_t)(bn + row)*K + k0 + cc*8); }
        CPA_COMMIT();
    };

    float acc[2][4][4];
    #pragma unroll
    for (int mt = 0; mt < 2; mt++)
        #pragma unroll
        for (int nt = 0; nt < 4; nt++)
            #pragma unroll
            for (int e = 0; e < 4; e++) acc[mt][nt][e] = 0.f;

    const int T = K >> 5;
    issue(0); issue(1);

    for (int t = 0; t < T; t++) {
        if (t + 1 < T) { CPA_WAIT1(); } else { CPA_WAIT0(); }
        __syncthreads();
        if (t + 2 < T) issue(t + 2);

        const uint32_t ab = sb + ((t % 3) * GSTG_H) * 2;
        const uint32_t bb = ab + GA_HSZ * 2;
        #pragma unroll
        for (int ks = 0; ks < 2; ks++) {
            uint32_t a[2][4];
            #pragma unroll
            for (int mt = 0; mt < 2; mt++) {
                const uint32_t ad = ab +
                    ((wm*32 + mt*16 + (lane & 15))*GASTR + ks*16 + (lane >> 4)*8)*2;
                LDMX4(a[mt][0], a[mt][1], a[mt][2], a[mt][3], ad);
            }
            uint32_t b[4][2];
            #pragma unroll
            for (int p = 0; p < 2; p++) {
                const uint32_t bd = bb +
                    ((wn*32 + p*16 + (lane & 7) + ((lane >> 4) & 1)*8)*GASTR
                     + ks*16 + ((lane >> 3) & 1)*8)*2;
                LDMX4(b[2*p][0], b[2*p][1], b[2*p+1][0], b[2*p+1][1], bd);
            }
            #pragma unroll
            for (int mt = 0; mt < 2; mt++)
                #pragma unroll
                for (int nt = 0; nt < 4; nt++)
                    mma16(acc[mt][nt], a[mt][0], a[mt][1], a[mt][2], a[mt][3],
                          b[nt][0], b[nt][1]);
        }
    }

    #pragma unroll
    for (int mt = 0; mt < 2; mt++) {
        const int r0 = bm + wm*32 + mt*16 + g;
        #pragma unroll
        for (int nt = 0; nt < 4; nt++) {
            const int cc = bn + wn*32 + nt*8 + 2*tg;
            const float b0 = bias[cc], b1 = bias[cc + 1];
            float v00 = acc[mt][nt][0] + b0, v01 = acc[mt][nt][1] + b1;
            float v10 = acc[mt][nt][2] + b0, v11 = acc[mt][nt][3] + b1;
            const size_t off0 = (size_t)r0*Dd + cc;
            const size_t off1 = (size_t)(r0 + 8)*Dd + cc;
            if (RES) {
                float2 p0 = *(const float2*)(res + off0);
                float2 p1 = *(const float2*)(res + off1);
                v00 += p0.x; v01 += p0.y; v10 += p1.x; v11 += p1.y;
            }
            if (WF32) {
                float2 o0; o0.x = v00; o0.y = v01;
                float2 o1; o1.x = v10; o1.y = v11;
                *(float2*)(C32 + off0) = o0;
                *(float2*)(C32 + off1) = o1;
            }
            *(uint32_t*)(C16 + off0) = pk(v00*scale, v01*scale);
            *(uint32_t*)(C16 + off1) = pk(v10*scale, v11*scale);
        }
    }
}

__global__ __launch_bounds__(256)
void gemm_in(const __half* A16, const __half* WT, const float* bias,
             float* C32, __half* C16, int K) {
    gemm16_body<false, true>(A16, WT, bias, nullptr, C32, C16, 1.f, K,
                             blockIdx.x*128, blockIdx.y*64);
}

__global__ __launch_bounds__(256)
void gemm_qkv(const __half* h16, const __half* w16t,
              const float* qb, const float* kb, const float* vb,
              __half* q16, __half* k16, __half* v16, int l) {
    const int z = blockIdx.z;
    const __half* WT = w16t + WOFF_L(l, z);
    const float* bi  = (z == 0) ? qb : (z == 1) ? kb : vb;
    __half*      C16 = (z == 0) ? q16 : (z == 1) ? k16 : v16;
    const float  sc  = (z == 0) ? 0.125f : 1.f;
    gemm16_body<false, false>(h16, WT, bi, nullptr, nullptr, C16, sc, Dd,
                              blockIdx.x*128, blockIdx.y*64);
}

__global__ __launch_bounds__(256)
void gemm_o(const __half* ao16, const __half* WT, const float* bias,
            const float* res, float* C32, __half* C16) {
    gemm16_body<true, true>(ao16, WT, bias, res, C32, C16, 1.f, Dd,
                            blockIdx.x*128, blockIdx.y*64);
}

// ---------------------------------------------------------------------------
// fp16 flash attention. CTA = (head, 128-row i-tile, batch), 8 warps.
// Same race fix on the final j-tile (jt==15 -> wait_group 0).
// ---------------------------------------------------------------------------
#define ATSTR   72
#define AQ_HSZ  (128*ATSTR)           // 9216
#define AKV_HSZ (64*ATSTR)            // 4608
#define ASTG_H  (2*AKV_HSZ)           // 9216 / stage
#define ATTN_SMEM ((AQ_HSZ + 3*ASTG_H)*2)   // 73728 B

__global__ __launch_bounds__(256)
void attn16(const __half* __restrict__ q16, const __half* __restrict__ k16,
            const __half* __restrict__ v16, const float* __restrict__ bias_l,
            __half* __restrict__ ao16) {
    extern __shared__ __half smh[];
    const uint32_t sb = smem_u32(smh);
    const int tid  = threadIdx.x;
    const int lane = tid & 31;
    const int w    = tid >> 5;
    const int g    = lane >> 2;
    const int tg   = lane & 3;
    const int hh   = blockIdx.x;
    const int i0   = blockIdx.y * 128;
    const int bb   = blockIdx.z;
    const int w16r = w * 16;

    auto issueKV = [&](int jt) {
        const uint32_t kb = sb + (AQ_HSZ + (jt % 3) * ASTG_H) * 2;
        const uint32_t vb = kb + AKV_HSZ * 2;
        #pragma unroll
        for (int c = tid; c < 512; c += 256) {
            const int row = c >> 3, cc = c & 7;
            const size_t go = (size_t)(bb*Nn + jt*64 + row)*Dd + hh*HDd + cc*8;
            cpa16(kb + (row*ATSTR + cc*8)*2, k16 + go);
            cpa16(vb + (row*ATSTR + cc*8)*2, v16 + go);
        }
        CPA_COMMIT();
    };

    // group 0: Q + KV(0); group 1: KV(1)
    {
        #pragma unroll
        for (int c = tid; c < 1024; c += 256) {
            const int row = c >> 3, cc = c & 7;
            cpa16(sb + (row*ATSTR + cc*8)*2,
                  q16 + (size_t)(bb*Nn + i0 + row)*Dd + hh*HDd + cc*8);
        }
        const uint32_t kb = sb + AQ_HSZ*2;
        const uint32_t vb = kb + AKV_HSZ*2;
        #pragma unroll
        for (int c = tid; c < 512; c += 256) {
            const int row = c >> 3, cc = c & 7;
            const size_t go = (size_t)(bb*Nn + row)*Dd + hh*HDd + cc*8;
            cpa16(kb + (row*ATSTR + cc*8)*2, k16 + go);
            cpa16(vb + (row*ATSTR + cc*8)*2, v16 + go);
        }
        CPA_COMMIT();
        issueKV(1);
    }

    float o[8][4];
    #pragma unroll
    for (int dt = 0; dt < 8; dt++)
        #pragma unroll
        for (int e = 0; e < 4; e++) o[dt][e] = 0.f;
    float m0 = -1e30f, m1 = -1e30f, l0 = 0.f, l1 = 0.f;

    const int r0g = i0 + w16r + g;
    const float* bp0 = bias_l + ((size_t)(bb*Hh + hh) << 20) + (size_t)r0g*Nn;
    const float* bp1 = bp0 + 8*(size_t)Nn;

    for (int jt = 0; jt < 16; jt++) {
        // bias (fp32) — LDGs issued before the cp.async wait, consumed at s-init
        float2 bw0[8], bw1[8];
        #pragma unroll
        for (int nt = 0; nt < 8; nt++) {
            bw0[nt] = *(const float2*)(bp0 + jt*64 + nt*8 + 2*tg);
            bw1[nt] = *(const float2*)(bp1 + jt*64 + nt*8 + 2*tg);
        }

        if (jt + 1 < 16) { CPA_WAIT1(); } else { CPA_WAIT0(); }
        __syncthreads();
        if (jt + 2 < 16) issueKV(jt + 2);

        const uint32_t kbm = sb + (AQ_HSZ + (jt % 3) * ASTG_H) * 2;
        const uint32_t vbm = kbm + AKV_HSZ * 2;

        // S initialized from bias; QK MMAs accumulate on top
        float s[8][4];
        #pragma unroll
        for (int nt = 0; nt < 8; nt++) {
            s[nt][0] = bw0[nt].x; s[nt][1] = bw0[nt].y;
            s[nt][2] = bw1[nt].x; s[nt][3] = bw1[nt].y;
        }

        #pragma unroll
        for (int ks = 0; ks < 4; ks++) {
            uint32_t qa[4];
            const uint32_t qad = sb +
                ((w16r + (lane & 15))*ATSTR + ks*16 + (lane >> 4)*8)*2;
            LDMX4(qa[0], qa[1], qa[2], qa[3], qad);
            #pragma unroll
            for (int p = 0; p < 4; p++) {
                uint32_t b0, b1, b2, b3;
                const uint32_t kad = kbm +
                    ((p*16 + (lane & 7) + ((lane >> 4) & 1)*8)*ATSTR
                     + ks*16 + ((lane >> 3) & 1)*8)*2;
                LDMX4(b0, b1, b2, b3, kad);
                mma16(s[2*p],   qa[0], qa[1], qa[2], qa[3], b0, b1);
                mma16(s[2*p+1], qa[0], qa[1], qa[2], qa[3], b2, b3);
            }
        }

        // online softmax
        float mt0 = -1e30f, mt1 = -1e30f;
        #pragma unroll
        for (int nt = 0; nt < 8; nt++) {
            mt0 = fmaxf(mt0, fmaxf(s[nt][0], s[nt][1]));
            mt1 = fmaxf(mt1, fmaxf(s[nt][2], s[nt][3]));
        }
        mt0 = fmaxf(mt0, __shfl_xor_sync(0xffffffffu, mt0, 1));
        mt0 = fmaxf(mt0, __shfl_xor_sync(0xffffffffu, mt0, 2));
        mt1 = fmaxf(mt1, __shfl_xor_sync(0xffffffffu, mt1, 1));
        mt1 = fmaxf(mt1, __shfl_xor_sync(0xffffffffu, mt1, 2));
        const float mn0 = fmaxf(m0, mt0), mn1 = fmaxf(m1, mt1);
        const float al0 = __expf(m0 - mn0), al1 = __expf(m1 - mn1);
        m0 = mn0; m1 = mn1;
        float rs0 = 0.f, rs1 = 0.f;
        #pragma unroll
        for (int nt = 0; nt < 8; nt++) {
            s[nt][0] = __expf(s[nt][0] - mn0); rs0 += s[nt][0];
            s[nt][1] = __expf(s[nt][1] - mn0); rs0 += s[nt][1];
            s[nt][2] = __expf(s[nt][2] - mn1); rs1 += s[nt][2];
            s[nt][3] = __expf(s[nt][3] - mn1); rs1 += s[nt][3];
        }
        rs0 += __shfl_xor_sync(0xffffffffu, rs0, 1);
        rs0 += __shfl_xor_sync(0xffffffffu, rs0, 2);
        rs1 += __shfl_xor_sync(0xffffffffu, rs1, 1);
        rs1 += __shfl_xor_sync(0xffffffffu, rs1, 2);
        l0 = l0*al0 + rs0; l1 = l1*al1 + rs1;
        #pragma unroll
        for (int dt = 0; dt < 8; dt++) {
            o[dt][0] *= al0; o[dt][1] *= al0;
            o[dt][2] *= al1; o[dt][3] *= al1;
        }

        // O += P @ V : P fragments straight from registers (C-frag == A-frag)
        #pragma unroll
        for (int c = 0; c < 4; c++) {
            const uint32_t pa0 = pk(s[2*c][0],   s[2*c][1]);
            const uint32_t pa1 = pk(s[2*c][2],   s[2*c][3]);
            const uint32_t pa2 = pk(s[2*c+1][0], s[2*c+1][1]);
            const uint32_t pa3 = pk(s[2*c+1][2], s[2*c+1][3]);
            #pragma unroll
            for (int pd = 0; pd < 4; pd++) {
                uint32_t v0, v1, v2, v3;
                const uint32_t vad = vbm +
                    ((c*16 + (lane & 7) + ((lane >> 3) & 1)*8)*ATSTR
                     + pd*16 + ((lane >> 4) & 1)*8)*2;
                LDMX4T(v0, v1, v2, v3, vad);
                mma16(o[2*pd],   pa0, pa1, pa2, pa3, v0, v1);
                mma16(o[2*pd+1], pa0, pa1, pa2, pa3, v2, v3);
            }
        }
    }

    const float inv0 = 1.f / l0, inv1 = 1.f / l1;
    __half* op0 = ao16 + (size_t)(bb*Nn + r0g    )*Dd + hh*HDd;
    __half* op1 = ao16 + (size_t)(bb*Nn + r0g + 8)*Dd + hh*HDd;
    #pragma unroll
    for (int dt = 0; dt < 8; dt++) {
        const int dc = dt*8 + 2*tg;
        *(uint32_t*)(op0 + dc) = pk(o[dt][0]*inv0, o[dt][1]*inv0);
        *(uint32_t*)(op1 + dc) = pk(o[dt][2]*inv1, o[dt][3]*inv1);
    }
}

// ---------------------------------------------------------------------------
// LayerNorm: one block (128 threads) per row of 512.
// ---------------------------------------------------------------------------
__global__ __launch_bounds__(128)
void ln_kernel(const float* __restrict__ h, const float* __restrict__ g,
               const float* __restrict__ b, float* __restrict__ out) {
    const int row = blockIdx.x;
    const int tid = threadIdx.x;
    const float4 x = *(const float4*)(h + (size_t)row*Dd + tid*4);
    float s  = x.x + x.y + x.z + x.w;
    float s2 = x.x*x.x + x.y*x.y + x.z*x.z + x.w*x.w;
    #pragma unroll
    for (int off = 16; off >= 1; off >>= 1) {
        s  += __shfl_xor_sync(0xffffffffu, s,  off);
        s2 += __shfl_xor_sync(0xffffffffu, s2, off);
    }
    __shared__ float ws[4], ws2[4];
    if ((tid & 31) == 0) { ws[tid>>5] = s; ws2[tid>>5] = s2; }
    __syncthreads();
    s  = ws[0] + ws[1] + ws[2] + ws[3];
    s2 = ws2[0] + ws2[1] + ws2[2] + ws2[3];
    const float mu  = s * (1.f/Dd);
    const float var = s2 * (1.f/Dd) - mu*mu;
    const float rstd = rsqrtf(var + 1e-5f);
    const float4 g4 = *(const float4*)(g + tid*4);
    const float4 b4 = *(const float4*)(b + tid*4);
    float4 r;
    r.x = (x.x - mu)*rstd*g4.x + b4.x;
    r.y = (x.y - mu)*rstd*g4.y + b4.y;
    r.z = (x.z - mu)*rstd*g4.z + b4.z;
    r.w = (x.w - mu)*rstd*g4.w + b4.w;
    *(float4*)(out + (size_t)row*Dd + tid*4) = r;
}

// ---------------------------------------------------------------------------
extern "C" void kernel_launch(void* const* d_in, const int* in_sizes, int n_in,
                              void* d_out, int out_size) {
    (void)in_sizes; (void)n_in; (void)out_size;
    const float* x    = (const float*)d_in[0];
    const float* edges= (const float*)d_in[1];
    const float* in_w = (const float*)d_in[2];
    const float* in_b = (const float*)d_in[3];
    const float* qw   = (const float*)d_in[4];
    const float* qb   = (const float*)d_in[5];
    const float* kw   = (const float*)d_in[6];
    const float* kb   = (const float*)d_in[7];
    const float* vw   = (const float*)d_in[8];
    const float* vb   = (const float*)d_in[9];
    const float* ow   = (const float*)d_in[10];
    const float* ob   = (const float*)d_in[11];
    const float* ew   = (const float*)d_in[12];
    const float* eb   = (const float*)d_in[13];
    const float* ln_g = (const float*)d_in[14];
    const float* ln_b = (const float*)d_in[15];
    float* out = (float*)d_out;

    float *h, *bias32;
    __half *h16, *x16, *q16, *k16, *v16, *ao16, *w16t;
    cudaGetSymbolAddress((void**)&h,     g_h);
    cudaGetSymbolAddress((void**)&h16,   g_h16);
    cudaGetSymbolAddress((void**)&x16,   g_x16);
    cudaGetSymbolAddress((void**)&q16,   g_q16);
    cudaGetSymbolAddress((void**)&k16,   g_k16);
    cudaGetSymbolAddress((void**)&v16,   g_v16);
    cudaGetSymbolAddress((void**)&ao16,  g_ao16);
    cudaGetSymbolAddress((void**)&w16t,  g_w16t);
    cudaGetSymbolAddress((void**)&bias32,g_bias32);

    cudaFuncSetAttribute(gemm_in,  cudaFuncAttributeMaxDynamicSharedMemorySize, GEMM_SMEM);
    cudaFuncSetAttribute(gemm_qkv, cudaFuncAttributeMaxDynamicSharedMemorySize, GEMM_SMEM);
    cudaFuncSetAttribute(gemm_o,   cudaFuncAttributeMaxDynamicSharedMemorySize, GEMM_SMEM);
    cudaFuncSetAttribute(attn16,   cudaFuncAttributeMaxDynamicSharedMemorySize, ATTN_SMEM);

    // pre-passes
    wtrans<<<dim3(16,16,13), dim3(32,8)>>>(in_w, qw, kw, vw, ow, w16t);
    cvt_x16<<<BNROWS*IND/(256*8), 256>>>(x, x16);
    edgeproj<<<Bsz*Nn*(Nn/8)/256, 256>>>(edges, ew, eb, bias32);

    dim3 gg(BNROWS/128, Dd/64);            // (32, 8)
    dim3 gq(BNROWS/128, Dd/64, 3);
    dim3 ag(Hh, Nn/128, Bsz);              // (8, 8, 4)

    gemm_in<<<gg, 256, GEMM_SMEM>>>(x16, w16t, in_b, h, h16, IND);

    for (int l = 0; l < Ll; l++) {
        gemm_qkv<<<gq, 256, GEMM_SMEM>>>(h16, w16t, qb + l*Dd, kb + l*Dd, vb + l*Dd,
                                         q16, k16, v16, l);
        attn16<<<ag, 256, ATTN_SMEM>>>(q16, k16, v16,
                                       bias32 + (size_t)l*Bsz*Hh*Nn*Nn, ao16);
        gemm_o<<<gg, 256, GEMM_SMEM>>>(ao16, w16t + WOFF_L(l,3), ob + l*Dd,
                                       h, h, h16);
    }

    ln_kernel<<<BNROWS, 128>>>(h, ln_g, ln_b, out);
}

// round 12
// speedup vs baseline: 2.2792x; 1.1970x over previous
#include <cuda_runtime.h>
#include <cuda_fp16.h>
#include <math.h>
#include <stdint.h>

#define Bsz 4
#define Nn 1024
#define IND 128
#define Dd 512
#define Hh 8
#define HDd 64
#define Ee 4
#define Ll 3
#define BNROWS (Bsz*Nn)   // 4096

// ---------------------------------------------------------------------------
// Scratch (device globals: no cudaMalloc allowed)
// ---------------------------------------------------------------------------
__device__ float  g_h   [BNROWS*Dd];
__device__ __half g_h16 [BNROWS*Dd];
__device__ __half g_x16 [BNROWS*IND];
__device__ __half g_q16 [BNROWS*Dd];
__device__ __half g_k16 [BNROWS*Dd];
__device__ __half g_v16 [BNROWS*Dd];
__device__ __half g_ao16[BNROWS*Dd];
// transposed fp16 weights: in_w^T [512][128], then per (l, {q,k,v,o}): [512][512]
__device__ __half g_w16t[512*128 + 12*512*512];
// per-layer edge bias: [L][B][H][N][N] fp16 (R8's 3e-3 blame on fp16 was the
// cp.async drain race, fixed in R10; this is the clean fp16 experiment)
__device__ __half g_bias16[(size_t)Ll*Bsz*Hh*Nn*Nn];

#define WOFF_L(l, m) (512*128 + ((size_t)((l)*4 + (m)))*512*512)

// ---------------------------------------------------------------------------
// helpers
// ---------------------------------------------------------------------------
__device__ __forceinline__ uint32_t pk(float x, float y) {
    __half2 h = __floats2half2_rn(x, y);
    return *reinterpret_cast<uint32_t*>(&h);
}

__device__ __forceinline__ uint32_t smem_u32(const void* p) {
    uint32_t a;
    asm("{ .reg .u64 t; cvta.to.shared.u64 t, %1; cvt.u32.u64 %0, t; }"
        : "=r"(a) : "l"(p));
    return a;
}

__device__ __forceinline__ void mma16(float* c, uint32_t a0, uint32_t a1,
                                      uint32_t a2, uint32_t a3,
                                      uint32_t b0, uint32_t b1) {
    asm volatile(
        "mma.sync.aligned.m16n8k16.row.col.f32.f16.f16.f32 "
        "{%0,%1,%2,%3},{%4,%5,%6,%7},{%8,%9},{%0,%1,%2,%3};"
        : "+f"(c[0]), "+f"(c[1]), "+f"(c[2]), "+f"(c[3])
        : "r"(a0), "r"(a1), "r"(a2), "r"(a3), "r"(b0), "r"(b1));
}

#define LDMX4(r0,r1,r2,r3,addr) \
    asm volatile("ldmatrix.sync.aligned.m8n8.x4.shared.b16 {%0,%1,%2,%3}, [%4];" \
                 : "=r"(r0),"=r"(r1),"=r"(r2),"=r"(r3) : "r"(addr))
#define LDMX4T(r0,r1,r2,r3,addr) \
    asm volatile("ldmatrix.sync.aligned.m8n8.x4.trans.shared.b16 {%0,%1,%2,%3}, [%4];" \
                 : "=r"(r0),"=r"(r1),"=r"(r2),"=r"(r3) : "r"(addr))

__device__ __forceinline__ void cpa16(uint32_t dst, const void* src) {
    asm volatile("cp.async.cg.shared.global [%0], [%1], 16;" :: "r"(dst), "l"(src));
}
#define CPA_COMMIT() asm volatile("cp.async.commit_group;")
#define CPA_WAIT1()  asm volatile("cp.async.wait_group 1;")
#define CPA_WAIT0()  asm volatile("cp.async.wait_group 0;")

// ---------------------------------------------------------------------------
// Pre-pass 1: weight convert + transpose -> fp16 [n][k]
// ---------------------------------------------------------------------------
__global__ void wtrans(const float* __restrict__ in_w, const float* __restrict__ qw,
                       const float* __restrict__ kw, const float* __restrict__ vw,
                       const float* __restrict__ ow, __half* __restrict__ w16t) {
    const int z = blockIdx.z;
    const float* src; int K; size_t doff;
    if (z == 0) { src = in_w; K = IND; doff = 0; }
    else {
        const int li = (z - 1) >> 2, m = (z - 1) & 3;
        const float* base = (m == 0) ? qw : (m == 1) ? kw : (m == 2) ? vw : ow;
        src = base + (size_t)li * Dd * Dd;
        K = Dd; doff = 512*128 + (size_t)(z - 1) * 512 * 512;
    }
    const int k0 = blockIdx.x * 32, n0 = blockIdx.y * 32;
    if (k0 >= K) return;
    __shared__ float tile[32][33];
    const int tx = threadIdx.x, ty = threadIdx.y;
    #pragma unroll
    for (int i = 0; i < 4; i++)
        tile[ty + i*8][tx] = src[(size_t)(k0 + ty + i*8) * Dd + n0 + tx];
    __syncthreads();
    #pragma unroll
    for (int i = 0; i < 4; i++)
        w16t[doff + (size_t)(n0 + ty + i*8) * K + k0 + tx] =
            __float2half(tile[tx][ty + i*8]);
}

// Pre-pass 2: x -> fp16
__global__ void cvt_x16(const float* __restrict__ x, __half* __restrict__ x16) {
    const int i = (blockIdx.x * 256 + threadIdx.x) * 8;
    float4 a = *(const float4*)(x + i);
    float4 b = *(const float4*)(x + i + 4);
    uint4 u;
    u.x = pk(a.x, a.y); u.y = pk(a.z, a.w);
    u.z = pk(b.x, b.y); u.w = pk(b.z, b.w);
    *(uint4*)(x16 + i) = u;
}

// Pre-pass 3: edge bias for all layers (fp16): bias16[l][b][h][i][j]
__global__ void edgeproj(const float* __restrict__ edges, const float* __restrict__ ew,
                         const float* __restrict__ eb, __half* __restrict__ bias16) {
    const int t  = blockIdx.x * 256 + threadIdx.x;   // 524288 threads
    const int jo = t & 127;
    const int i  = (t >> 7) & 1023;
    const int b  = t >> 17;
    const float* ep = edges + (((size_t)b * Nn + i) * Nn + (size_t)jo * 8) * Ee;
    float e[8][4];
    #pragma unroll
    for (int p = 0; p < 8; p++) {
        float4 v = *(const float4*)(ep + p * 4);
        e[p][0] = v.x; e[p][1] = v.y; e[p][2] = v.z; e[p][3] = v.w;
    }
    #pragma unroll
    for (int l = 0; l < Ll; l++) {
        #pragma unroll
        for (int h = 0; h < Hh; h++) {
            const float w0 = ew[l*32 + h],      w1 = ew[l*32 + 8 + h];
            const float w2 = ew[l*32 + 16 + h], w3 = ew[l*32 + 24 + h];
            const float bb = eb[l*8 + h];
            float v[8];
            #pragma unroll
            for (int p = 0; p < 8; p++)
                v[p] = fmaf(e[p][0],w0, fmaf(e[p][1],w1, fmaf(e[p][2],w2,
                             fmaf(e[p][3],w3, bb))));
            uint4 u;
            u.x = pk(v[0],v[1]); u.y = pk(v[2],v[3]);
            u.z = pk(v[4],v[5]); u.w = pk(v[6],v[7]);
            *(uint4*)(bias16 + (((size_t)((l*Bsz + b)*Hh + h)) << 20)
                              + (size_t)i * Nn + jo * 8) = u;
        }
    }
}

// ---------------------------------------------------------------------------
// fp16 GEMM: C[M x 512] = A16[M x K] @ W16T^T + bias (+ res)
// CTA 128x64, BK=32, 3-stage cp.async, ldmatrix fragments.
// Final tile drains with wait_group 0 (R10 race fix).
// ---------------------------------------------------------------------------
#define GASTR 40
#define GA_HSZ (128*GASTR)        // 5120 halfs
#define GB_HSZ (64*GASTR)         // 2560 halfs
#define GSTG_H (GA_HSZ + GB_HSZ)  // 7680 halfs / stage
#define GEMM_SMEM (3*GSTG_H*2)    // 46080 B

template<bool RES, bool WF32>
__device__ __forceinline__
void gemm16_body(const __half* __restrict__ A16, const __half* __restrict__ WT,
                 const float* __restrict__ bias, const float* __restrict__ res,
                 float* __restrict__ C32, __half* __restrict__ C16,
                 float scale, int K, int bm, int bn) {
    extern __shared__ __half smh[];
    const uint32_t sb = smem_u32(smh);
    const int tid  = threadIdx.x;
    const int lane = tid & 31;
    const int warp = tid >> 5;
    const int wm   = warp & 3;
    const int wn   = warp >> 2;
    const int g    = lane >> 2;
    const int tg   = lane & 3;

    auto issue = [&](int t) {
        const int k0 = t << 5;
        const uint32_t ab = sb + ((t % 3) * GSTG_H) * 2;
        const uint32_t bb = ab + GA_HSZ * 2;
        #pragma unroll
        for (int c = tid; c < 512; c += 256) {
            const int row = c >> 2, cc = c & 3;
            cpa16(ab + (row*GASTR + cc*8)*2,
                  A16 + (size_t)(bm + row)*K + k0 + cc*8);
        }
        { const int row = tid >> 2, cc = tid & 3;
          cpa16(bb + (row*GASTR + cc*8)*2,
                WT + (size_t)(bn + row)*K + k0 + cc*8); }
        CPA_COMMIT();
    };

    float acc[2][4][4];
    #pragma unroll
    for (int mt = 0; mt < 2; mt++)
        #pragma unroll
        for (int nt = 0; nt < 4; nt++)
            #pragma unroll
            for (int e = 0; e < 4; e++) acc[mt][nt][e] = 0.f;

    const int T = K >> 5;
    issue(0); issue(1);

    for (int t = 0; t < T; t++) {
        if (t + 1 < T) { CPA_WAIT1(); } else { CPA_WAIT0(); }
        __syncthreads();
        if (t + 2 < T) issue(t + 2);

        const uint32_t ab = sb + ((t % 3) * GSTG_H) * 2;
        const uint32_t bb = ab + GA_HSZ * 2;
        #pragma unroll
        for (int ks = 0; ks < 2; ks++) {
            uint32_t a[2][4];
            #pragma unroll
            for (int mt = 0; mt < 2; mt++) {
                const uint32_t ad = ab +
                    ((wm*32 + mt*16 + (lane & 15))*GASTR + ks*16 + (lane >> 4)*8)*2;
                LDMX4(a[mt][0], a[mt][1], a[mt][2], a[mt][3], ad);
            }
            uint32_t b[4][2];
            #pragma unroll
            for (int p = 0; p < 2; p++) {
                const uint32_t bd = bb +
                    ((wn*32 + p*16 + (lane & 7) + ((lane >> 4) & 1)*8)*GASTR
                     + ks*16 + ((lane >> 3) & 1)*8)*2;
                LDMX4(b[2*p][0], b[2*p][1], b[2*p+1][0], b[2*p+1][1], bd);
            }
            #pragma unroll
            for (int mt = 0; mt < 2; mt++)
                #pragma unroll
                for (int nt = 0; nt < 4; nt++)
                    mma16(acc[mt][nt], a[mt][0], a[mt][1], a[mt][2], a[mt][3],
                          b[nt][0], b[nt][1]);
        }
    }

    #pragma unroll
    for (int mt = 0; mt < 2; mt++) {
        const int r0 = bm + wm*32 + mt*16 + g;
        #pragma unroll
        for (int nt = 0; nt < 4; nt++) {
            const int cc = bn + wn*32 + nt*8 + 2*tg;
            const float b0 = bias[cc], b1 = bias[cc + 1];
            float v00 = acc[mt][nt][0] + b0, v01 = acc[mt][nt][1] + b1;
            float v10 = acc[mt][nt][2] + b0, v11 = acc[mt][nt][3] + b1;
            const size_t off0 = (size_t)r0*Dd + cc;
            const size_t off1 = (size_t)(r0 + 8)*Dd + cc;
            if (RES) {
                float2 p0 = *(const float2*)(res + off0);
                float2 p1 = *(const float2*)(res + off1);
                v00 += p0.x; v01 += p0.y; v10 += p1.x; v11 += p1.y;
            }
            if (WF32) {
                float2 o0; o0.x = v00; o0.y = v01;
                float2 o1; o1.x = v10; o1.y = v11;
                *(float2*)(C32 + off0) = o0;
                *(float2*)(C32 + off1) = o1;
            }
            *(uint32_t*)(C16 + off0) = pk(v00*scale, v01*scale);
            *(uint32_t*)(C16 + off1) = pk(v10*scale, v11*scale);
        }
    }
}

__global__ __launch_bounds__(256)
void gemm_in(const __half* A16, const __half* WT, const float* bias,
             float* C32, __half* C16, int K) {
    gemm16_body<false, true>(A16, WT, bias, nullptr, C32, C16, 1.f, K,
                             blockIdx.x*128, blockIdx.y*64);
}

__global__ __launch_bounds__(256)
void gemm_qkv(const __half* h16, const __half* w16t,
              const float* qb, const float* kb, const float* vb,
              __half* q16, __half* k16, __half* v16, int l) {
    const int z = blockIdx.z;
    const __half* WT = w16t + WOFF_L(l, z);
    const float* bi  = (z == 0) ? qb : (z == 1) ? kb : vb;
    __half*      C16 = (z == 0) ? q16 : (z == 1) ? k16 : v16;
    const float  sc  = (z == 0) ? 0.125f : 1.f;
    gemm16_body<false, false>(h16, WT, bi, nullptr, nullptr, C16, sc, Dd,
                              blockIdx.x*128, blockIdx.y*64);
}

__global__ __launch_bounds__(256)
void gemm_o(const __half* ao16, const __half* WT, const float* bias,
            const float* res, float* C32, __half* C16) {
    gemm16_body<true, true>(ao16, WT, bias, res, C32, C16, 1.f, Dd,
                            blockIdx.x*128, blockIdx.y*64);
}

// ---------------------------------------------------------------------------
// fp16 flash attention. CTA = (head, 128-row i-tile, batch), 8 warps.
// fp16 precomputed bias initializes S; final j-tile drains with wait_group 0.
// ---------------------------------------------------------------------------
#define ATSTR   72
#define AQ_HSZ  (128*ATSTR)           // 9216
#define AKV_HSZ (64*ATSTR)            // 4608
#define ASTG_H  (2*AKV_HSZ)           // 9216 / stage
#define ATTN_SMEM ((AQ_HSZ + 3*ASTG_H)*2)   // 73728 B

__global__ __launch_bounds__(256)
void attn16(const __half* __restrict__ q16, const __half* __restrict__ k16,
            const __half* __restrict__ v16, const __half* __restrict__ bias_l,
            __half* __restrict__ ao16) {
    extern __shared__ __half smh[];
    const uint32_t sb = smem_u32(smh);
    const int tid  = threadIdx.x;
    const int lane = tid & 31;
    const int w    = tid >> 5;
    const int g    = lane >> 2;
    const int tg   = lane & 3;
    const int hh   = blockIdx.x;
    const int i0   = blockIdx.y * 128;
    const int bb   = blockIdx.z;
    const int w16r = w * 16;

    auto issueKV = [&](int jt) {
        const uint32_t kb = sb + (AQ_HSZ + (jt % 3) * ASTG_H) * 2;
        const uint32_t vb = kb + AKV_HSZ * 2;
        #pragma unroll
        for (int c = tid; c < 512; c += 256) {
            const int row = c >> 3, cc = c & 7;
            const size_t go = (size_t)(bb*Nn + jt*64 + row)*Dd + hh*HDd + cc*8;
            cpa16(kb + (row*ATSTR + cc*8)*2, k16 + go);
            cpa16(vb + (row*ATSTR + cc*8)*2, v16 + go);
        }
        CPA_COMMIT();
    };

    // group 0: Q + KV(0); group 1: KV(1)
    {
        #pragma unroll
        for (int c = tid; c < 1024; c += 256) {
            const int row = c >> 3, cc = c & 7;
            cpa16(sb + (row*ATSTR + cc*8)*2,
                  q16 + (size_t)(bb*Nn + i0 + row)*Dd + hh*HDd + cc*8);
        }
        const uint32_t kb = sb + AQ_HSZ*2;
        const uint32_t vb = kb + AKV_HSZ*2;
        #pragma unroll
        for (int c = tid; c < 512; c += 256) {
            const int row = c >> 3, cc = c & 7;
            const size_t go = (size_t)(bb*Nn + row)*Dd + hh*HDd + cc*8;
            cpa16(kb + (row*ATSTR + cc*8)*2, k16 + go);
            cpa16(vb + (row*ATSTR + cc*8)*2, v16 + go);
        }
        CPA_COMMIT();
        issueKV(1);
    }

    float o[8][4];
    #pragma unroll
    for (int dt = 0; dt < 8; dt++)
        #pragma unroll
        for (int e = 0; e < 4; e++) o[dt][e] = 0.f;
    float m0 = -1e30f, m1 = -1e30f, l0 = 0.f, l1 = 0.f;

    const int r0g = i0 + w16r + g;
    const __half* bp0 = bias_l + ((size_t)(bb*Hh + hh) << 20) + (size_t)r0g*Nn;
    const __half* bp1 = bp0 + 8*(size_t)Nn;

    for (int jt = 0; jt < 16; jt++) {
        // bias (fp16x2 words) — LDGs issued before the cp.async wait
        uint32_t bw0[8], bw1[8];
        #pragma unroll
        for (int nt = 0; nt < 8; nt++) {
            bw0[nt] = *(const uint32_t*)(bp0 + jt*64 + nt*8 + 2*tg);
            bw1[nt] = *(const uint32_t*)(bp1 + jt*64 + nt*8 + 2*tg);
        }

        if (jt + 1 < 16) { CPA_WAIT1(); } else { CPA_WAIT0(); }
        __syncthreads();
        if (jt + 2 < 16) issueKV(jt + 2);

        const uint32_t kbm = sb + (AQ_HSZ + (jt % 3) * ASTG_H) * 2;
        const uint32_t vbm = kbm + AKV_HSZ * 2;

        // S initialized from bias; QK MMAs accumulate on top
        float s[8][4];
        #pragma unroll
        for (int nt = 0; nt < 8; nt++) {
            const float2 f0 = __half22float2(*reinterpret_cast<__half2*>(&bw0[nt]));
            const float2 f1 = __half22float2(*reinterpret_cast<__half2*>(&bw1[nt]));
            s[nt][0] = f0.x; s[nt][1] = f0.y;
            s[nt][2] = f1.x; s[nt][3] = f1.y;
        }

        #pragma unroll
        for (int ks = 0; ks < 4; ks++) {
            uint32_t qa[4];
            const uint32_t qad = sb +
                ((w16r + (lane & 15))*ATSTR + ks*16 + (lane >> 4)*8)*2;
            LDMX4(qa[0], qa[1], qa[2], qa[3], qad);
            #pragma unroll
            for (int p = 0; p < 4; p++) {
                uint32_t b0, b1, b2, b3;
                const uint32_t kad = kbm +
                    ((p*16 + (lane & 7) + ((lane >> 4) & 1)*8)*ATSTR
                     + ks*16 + ((lane >> 3) & 1)*8)*2;
                LDMX4(b0, b1, b2, b3, kad);
                mma16(s[2*p],   qa[0], qa[1], qa[2], qa[3], b0, b1);
                mma16(s[2*p+1], qa[0], qa[1], qa[2], qa[3], b2, b3);
            }
        }

        // online softmax
        float mt0 = -1e30f, mt1 = -1e30f;
        #pragma unroll
        for (int nt = 0; nt < 8; nt++) {
            mt0 = fmaxf(mt0, fmaxf(s[nt][0], s[nt][1]));
            mt1 = fmaxf(mt1, fmaxf(s[nt][2], s[nt][3]));
        }
        mt0 = fmaxf(mt0, __shfl_xor_sync(0xffffffffu, mt0, 1));
        mt0 = fmaxf(mt0, __shfl_xor_sync(0xffffffffu, mt0, 2));
        mt1 = fmaxf(mt1, __shfl_xor_sync(0xffffffffu, mt1, 1));
        mt1 = fmaxf(mt1, __shfl_xor_sync(0xffffffffu, mt1, 2));
        const float mn0 = fmaxf(m0, mt0), mn1 = fmaxf(m1, mt1);
        const float al0 = __expf(m0 - mn0), al1 = __expf(m1 - mn1);
        m0 = mn0; m1 = mn1;
        float rs0 = 0.f, rs1 = 0.f;
        #pragma unroll
        for (int nt = 0; nt < 8; nt++) {
            s[nt][0] = __expf(s[nt][0] - mn0); rs0 += s[nt][0];
            s[nt][1] = __expf(s[nt][1] - mn0); rs0 += s[nt][1];
            s[nt][2] = __expf(s[nt][2] - mn1); rs1 += s[nt][2];
            s[nt][3] = __expf(s[nt][3] - mn1); rs1 += s[nt][3];
        }
        rs0 += __shfl_xor_sync(0xffffffffu, rs0, 1);
        rs0 += __shfl_xor_sync(0xffffffffu, rs0, 2);
        rs1 += __shfl_xor_sync(0xffffffffu, rs1, 1);
        rs1 += __shfl_xor_sync(0xffffffffu, rs1, 2);
        l0 = l0*al0 + rs0; l1 = l1*al1 + rs1;
        #pragma unroll
        for (int dt = 0; dt < 8; dt++) {
            o[dt][0] *= al0; o[dt][1] *= al0;
            o[dt][2] *= al1; o[dt][3] *= al1;
        }

        // O += P @ V : P fragments straight from registers (C-frag == A-frag)
        #pragma unroll
        for (int c = 0; c < 4; c++) {
            const uint32_t pa0 = pk(s[2*c][0],   s[2*c][1]);
            const uint32_t pa1 = pk(s[2*c][2],   s[2*c][3]);
            const uint32_t pa2 = pk(s[2*c+1][0], s[2*c+1][1]);
            const uint32_t pa3 = pk(s[2*c+1][2], s[2*c+1][3]);
            #pragma unroll
            for (int pd = 0; pd < 4; pd++) {
                uint32_t v0, v1, v2, v3;
                const uint32_t vad = vbm +
                    ((c*16 + (lane & 7) + ((lane >> 3) & 1)*8)*ATSTR
                     + pd*16 + ((lane >> 4) & 1)*8)*2;
                LDMX4T(v0, v1, v2, v3, vad);
                mma16(o[2*pd],   pa0, pa1, pa2, pa3, v0, v1);
                mma16(o[2*pd+1], pa0, pa1, pa2, pa3, v2, v3);
            }
        }
    }

    const float inv0 = 1.f / l0, inv1 = 1.f / l1;
    __half* op0 = ao16 + (size_t)(bb*Nn + r0g    )*Dd + hh*HDd;
    __half* op1 = ao16 + (size_t)(bb*Nn + r0g + 8)*Dd + hh*HDd;
    #pragma unroll
    for (int dt = 0; dt < 8; dt++) {
        const int dc = dt*8 + 2*tg;
        *(uint32_t*)(op0 + dc) = pk(o[dt][0]*inv0, o[dt][1]*inv0);
        *(uint32_t*)(op1 + dc) = pk(o[dt][2]*inv1, o[dt][3]*inv1);
    }
}

// ---------------------------------------------------------------------------
// LayerNorm: one block (128 threads) per row of 512.
// ---------------------------------------------------------------------------
__global__ __launch_bounds__(128)
void ln_kernel(const float* __restrict__ h, const float* __restrict__ g,
               const float* __restrict__ b, float* __restrict__ out) {
    const int row = blockIdx.x;
    const int tid = threadIdx.x;
    const float4 x = *(const float4*)(h + (size_t)row*Dd + tid*4);
    float s  = x.x + x.y + x.z + x.w;
    float s2 = x.x*x.x + x.y*x.y + x.z*x.z + x.w*x.w;
    #pragma unroll
    for (int off = 16; off >= 1; off >>= 1) {
        s  += __shfl_xor_sync(0xffffffffu, s,  off);
        s2 += __shfl_xor_sync(0xffffffffu, s2, off);
    }
    __shared__ float ws[4], ws2[4];
    if ((tid & 31) == 0) { ws[tid>>5] = s; ws2[tid>>5] = s2; }
    __syncthreads();
    s  = ws[0] + ws[1] + ws[2] + ws[3];
    s2 = ws2[0] + ws2[1] + ws2[2] + ws2[3];
    const float mu  = s * (1.f/Dd);
    const float var = s2 * (1.f/Dd) - mu*mu;
    const float rstd = rsqrtf(var + 1e-5f);
    const float4 g4 = *(const float4*)(g + tid*4);
    const float4 b4 = *(const float4*)(b + tid*4);
    float4 r;
    r.x = (x.x - mu)*rstd*g4.x + b4.x;
    r.y = (x.y - mu)*rstd*g4.y + b4.y;
    r.z = (x.z - mu)*rstd*g4.z + b4.z;
    r.w = (x.w - mu)*rstd*g4.w + b4.w;
    *(float4*)(out + (size_t)row*Dd + tid*4) = r;
}

// ---------------------------------------------------------------------------
extern "C" void kernel_launch(void* const* d_in, const int* in_sizes, int n_in,
                              void* d_out, int out_size) {
    (void)in_sizes; (void)n_in; (void)out_size;
    const float* x    = (const float*)d_in[0];
    const float* edges= (const float*)d_in[1];
    const float* in_w = (const float*)d_in[2];
    const float* in_b = (const float*)d_in[3];
    const float* qw   = (const float*)d_in[4];
    const float* qb   = (const float*)d_in[5];
    const float* kw   = (const float*)d_in[6];
    const float* kb   = (const float*)d_in[7];
    const float* vw   = (const float*)d_in[8];
    const float* vb   = (const float*)d_in[9];
    const float* ow   = (const float*)d_in[10];
    const float* ob   = (const float*)d_in[11];
    const float* ew   = (const float*)d_in[12];
    const float* eb   = (const float*)d_in[13];
    const float* ln_g = (const float*)d_in[14];
    const float* ln_b = (const float*)d_in[15];
    float* out = (float*)d_out;

    float *h;
    __half *h16, *x16, *q16, *k16, *v16, *ao16, *w16t, *bias16;
    cudaGetSymbolAddress((void**)&h,     g_h);
    cudaGetSymbolAddress((void**)&h16,   g_h16);
    cudaGetSymbolAddress((void**)&x16,   g_x16);
    cudaGetSymbolAddress((void**)&q16,   g_q16);
    cudaGetSymbolAddress((void**)&k16,   g_k16);
    cudaGetSymbolAddress((void**)&v16,   g_v16);
    cudaGetSymbolAddress((void**)&ao16,  g_ao16);
    cudaGetSymbolAddress((void**)&w16t,  g_w16t);
    cudaGetSymbolAddress((void**)&bias16,g_bias16);

    cudaFuncSetAttribute(gemm_in,  cudaFuncAttributeMaxDynamicSharedMemorySize, GEMM_SMEM);
    cudaFuncSetAttribute(gemm_qkv, cudaFuncAttributeMaxDynamicSharedMemorySize, GEMM_SMEM);
    cudaFuncSetAttribute(gemm_o,   cudaFuncAttributeMaxDynamicSharedMemorySize, GEMM_SMEM);
    cudaFuncSetAttribute(attn16,   cudaFuncAttributeMaxDynamicSharedMemorySize, ATTN_SMEM);

    // pre-passes
    wtrans<<<dim3(16,16,13), dim3(32,8)>>>(in_w, qw, kw, vw, ow, w16t);
    cvt_x16<<<BNROWS*IND/(256*8), 256>>>(x, x16);
    edgeproj<<<Bsz*Nn*(Nn/8)/256, 256>>>(edges, ew, eb, bias16);

    dim3 gg(BNROWS/128, Dd/64);            // (32, 8)
    dim3 gq(BNROWS/128, Dd/64, 3);
    dim3 ag(Hh, Nn/128, Bsz);              // (8, 8, 4)

    gemm_in<<<gg, 256, GEMM_SMEM>>>(x16, w16t, in_b, h, h16, IND);

    for (int l = 0; l < Ll; l++) {
        gemm_qkv<<<gq, 256, GEMM_SMEM>>>(h16, w16t, qb + l*Dd, kb + l*Dd, vb + l*Dd,
                                         q16, k16, v16, l);
        attn16<<<ag, 256, ATTN_SMEM>>>(q16, k16, v16,
                                       bias16 + (size_t)l*Bsz*Hh*Nn*Nn, ao16);
        gemm_o<<<gg, 256, GEMM_SMEM>>>(ao16, w16t + WOFF_L(l,3), ob + l*Dd,
                                       h, h, h16);
    }

    ln_kernel<<<BNROWS, 128>>>(h, ln_g, ln_b, out);
}